// round 2
// baseline (speedup 1.0000x reference)
#include <cuda_runtime.h>

#define B_  8
#define T_  512
#define C_  1024
#define NH_ 16
#define DH_ 64
#define HW_ 256

// Scratch (static device allocations are allowed; no cudaMalloc anywhere)
__device__ float g_Q[B_ * T_ * C_];
__device__ float g_K[B_ * T_ * C_];
__device__ float g_V[B_ * T_ * C_];
__device__ float g_Y[B_ * T_ * C_];
__device__ float g_Att[(size_t)B_ * NH_ * T_ * T_];

// ---------------------------------------------------------------------------
// C[m,n] = sum_k A[m,k] * W[n,k] + bias[n]       (A: MxK rm, W: NxK rm)
// Tile 128x128x16, 256 threads, 8x8 per thread.
// Requires M%128==0, N%128==0, K%16==0 (true for all uses here).
// ---------------------------------------------------------------------------
__global__ __launch_bounds__(256) void sgemm_abt(
    const float* __restrict__ A, const float* __restrict__ W,
    const float* __restrict__ bias, float* __restrict__ C,
    int M, int N, int K)
{
    __shared__ float As[16][132];
    __shared__ float Ws[16][132];
    const int tid = threadIdx.x;
    const int tx = tid & 15, ty = tid >> 4;
    const int m0 = blockIdx.y * 128, n0 = blockIdx.x * 128;

    float acc[8][8];
#pragma unroll
    for (int i = 0; i < 8; i++)
#pragma unroll
        for (int j = 0; j < 8; j++) acc[i][j] = 0.f;

    for (int k0 = 0; k0 < K; k0 += 16) {
#pragma unroll
        for (int it = 0; it < 2; it++) {
            int l = tid + it * 256;
            int row = l >> 2, c4 = (l & 3) * 4;
            float4 a = *(const float4*)(A + (size_t)(m0 + row) * K + k0 + c4);
            As[c4 + 0][row] = a.x; As[c4 + 1][row] = a.y;
            As[c4 + 2][row] = a.z; As[c4 + 3][row] = a.w;
            float4 w = *(const float4*)(W + (size_t)(n0 + row) * K + k0 + c4);
            Ws[c4 + 0][row] = w.x; Ws[c4 + 1][row] = w.y;
            Ws[c4 + 2][row] = w.z; Ws[c4 + 3][row] = w.w;
        }
        __syncthreads();
#pragma unroll
        for (int kk = 0; kk < 16; kk++) {
            float4 a0 = *(const float4*)&As[kk][ty * 8];
            float4 a1 = *(const float4*)&As[kk][ty * 8 + 4];
            float4 b0 = *(const float4*)&Ws[kk][tx * 8];
            float4 b1 = *(const float4*)&Ws[kk][tx * 8 + 4];
            float aa[8] = {a0.x, a0.y, a0.z, a0.w, a1.x, a1.y, a1.z, a1.w};
            float bb[8] = {b0.x, b0.y, b0.z, b0.w, b1.x, b1.y, b1.z, b1.w};
#pragma unroll
            for (int i = 0; i < 8; i++)
#pragma unroll
                for (int j = 0; j < 8; j++)
                    acc[i][j] = fmaf(aa[i], bb[j], acc[i][j]);
        }
        __syncthreads();
    }

#pragma unroll
    for (int i = 0; i < 8; i++) {
        int m = m0 + ty * 8 + i;
#pragma unroll
        for (int j = 0; j < 8; j += 4) {
            int n = n0 + tx * 8 + j;
            float4 o;
            o.x = acc[i][j]     + bias[n];
            o.y = acc[i][j + 1] + bias[n + 1];
            o.z = acc[i][j + 2] + bias[n + 2];
            o.w = acc[i][j + 3] + bias[n + 3];
            *(float4*)(C + (size_t)m * N + n) = o;
        }
    }
}

// ---------------------------------------------------------------------------
// S[bh,q,k] = 0.125 * dot(Q[b,h,q,:], K[b,h,k,:]), epipolar mask fused.
// 64x64 output tile per block, 256 threads, 4x4 per thread, Kdim=64.
// ---------------------------------------------------------------------------
__global__ __launch_bounds__(256) void qk_kernel(const float* __restrict__ fmap,
                                                 const float* __restrict__ bmap)
{
    const int bh = blockIdx.z, b = bh >> 4, h = bh & 15;
    const float* Qp = g_Q + (size_t)b * T_ * C_ + h * DH_;
    const float* Kp = g_K + (size_t)b * T_ * C_ + h * DH_;
    const int mt = blockIdx.y * 64, nt = blockIdx.x * 64;
    __shared__ float Qs[16][68];
    __shared__ float Ks[16][68];
    const int tid = threadIdx.x;
    const int tx = tid & 15, ty = tid >> 4;

    float acc[4][4];
#pragma unroll
    for (int i = 0; i < 4; i++)
#pragma unroll
        for (int j = 0; j < 4; j++) acc[i][j] = 0.f;

    for (int k0 = 0; k0 < DH_; k0 += 16) {
        int row = tid >> 2, c4 = (tid & 3) * 4;
        float4 q = *(const float4*)(Qp + (size_t)(mt + row) * C_ + k0 + c4);
        Qs[c4 + 0][row] = q.x; Qs[c4 + 1][row] = q.y;
        Qs[c4 + 2][row] = q.z; Qs[c4 + 3][row] = q.w;
        float4 kv = *(const float4*)(Kp + (size_t)(nt + row) * C_ + k0 + c4);
        Ks[c4 + 0][row] = kv.x; Ks[c4 + 1][row] = kv.y;
        Ks[c4 + 2][row] = kv.z; Ks[c4 + 3][row] = kv.w;
        __syncthreads();
#pragma unroll
        for (int kk = 0; kk < 16; kk++) {
            float4 a4 = *(const float4*)&Qs[kk][ty * 4];
            float4 v4 = *(const float4*)&Ks[kk][tx * 4];
            float aa[4] = {a4.x, a4.y, a4.z, a4.w};
            float bb[4] = {v4.x, v4.y, v4.z, v4.w};
#pragma unroll
            for (int i = 0; i < 4; i++)
#pragma unroll
                for (int j = 0; j < 4; j++)
                    acc[i][j] = fmaf(aa[i], bb[j], acc[i][j]);
        }
        __syncthreads();
    }

    float* out = g_Att + ((size_t)bh * T_ + mt) * T_ + nt;
#pragma unroll
    for (int i = 0; i < 4; i++) {
        int qg = mt + ty * 4 + i;
#pragma unroll
        for (int j = 0; j < 4; j++) {
            int kg = nt + tx * 4 + j;
            float s = acc[i][j] * 0.125f;
            if (qg < HW_ && kg < HW_)
                s *= fmap[((size_t)b * HW_ + qg) * HW_ + kg] *
                     bmap[((size_t)b * HW_ + kg) * HW_ + qg];
            out[(ty * 4 + i) * T_ + tx * 4 + j] = s;
        }
    }
}

// ---------------------------------------------------------------------------
// In-place softmax over rows of length 512. One block (128 threads) per row.
// ---------------------------------------------------------------------------
__global__ __launch_bounds__(128) void softmax512()
{
    __shared__ float red[4];
    const size_t row = blockIdx.x;
    float4* p = reinterpret_cast<float4*>(g_Att + row * T_);
    float4 v = p[threadIdx.x];
    const int lane = threadIdx.x & 31, w = threadIdx.x >> 5;

    float m = fmaxf(fmaxf(v.x, v.y), fmaxf(v.z, v.w));
#pragma unroll
    for (int o = 16; o > 0; o >>= 1) m = fmaxf(m, __shfl_xor_sync(0xffffffffu, m, o));
    if (lane == 0) red[w] = m;
    __syncthreads();
    m = fmaxf(fmaxf(red[0], red[1]), fmaxf(red[2], red[3]));
    __syncthreads();

    v.x = __expf(v.x - m); v.y = __expf(v.y - m);
    v.z = __expf(v.z - m); v.w = __expf(v.w - m);
    float s = v.x + v.y + v.z + v.w;
#pragma unroll
    for (int o = 16; o > 0; o >>= 1) s += __shfl_xor_sync(0xffffffffu, s, o);
    if (lane == 0) red[w] = s;
    __syncthreads();
    s = red[0] + red[1] + red[2] + red[3];

    float inv = 1.0f / s;
    v.x *= inv; v.y *= inv; v.z *= inv; v.w *= inv;
    p[threadIdx.x] = v;
}

// ---------------------------------------------------------------------------
// Y[b,q,h*64+d] = sum_k Att[bh,q,k] * V[b,k,h*64+d]
// 64(q) x 64(d) tile per block, 256 threads, 4x4 per thread, Kdim=512.
// ---------------------------------------------------------------------------
__global__ __launch_bounds__(256) void av_kernel()
{
    const int bh = blockIdx.y, b = bh >> 4, h = bh & 15;
    const int mt = blockIdx.x * 64;
    const float* Ap = g_Att + (size_t)bh * T_ * T_;
    const float* Vp = g_V + (size_t)b * T_ * C_ + h * DH_;
    __shared__ float As[16][68];
    __shared__ float Vs[16][68];
    const int tid = threadIdx.x;
    const int tx = tid & 15, ty = tid >> 4;

    float acc[4][4];
#pragma unroll
    for (int i = 0; i < 4; i++)
#pragma unroll
        for (int j = 0; j < 4; j++) acc[i][j] = 0.f;

    for (int k0 = 0; k0 < T_; k0 += 16) {
        int row = tid >> 2, c4 = (tid & 3) * 4;
        float4 a = *(const float4*)(Ap + (size_t)(mt + row) * T_ + k0 + c4);
        As[c4 + 0][row] = a.x; As[c4 + 1][row] = a.y;
        As[c4 + 2][row] = a.z; As[c4 + 3][row] = a.w;
        int kr = tid >> 4, n4 = (tid & 15) * 4;
        float4 v = *(const float4*)(Vp + (size_t)(k0 + kr) * C_ + n4);
        *(float4*)&Vs[kr][n4] = v;
        __syncthreads();
#pragma unroll
        for (int kk = 0; kk < 16; kk++) {
            float4 a4 = *(const float4*)&As[kk][ty * 4];
            float4 v4 = *(const float4*)&Vs[kk][tx * 4];
            float aa[4] = {a4.x, a4.y, a4.z, a4.w};
            float bb[4] = {v4.x, v4.y, v4.z, v4.w};
#pragma unroll
            for (int i = 0; i < 4; i++)
#pragma unroll
                for (int j = 0; j < 4; j++)
                    acc[i][j] = fmaf(aa[i], bb[j], acc[i][j]);
        }
        __syncthreads();
    }

#pragma unroll
    for (int i = 0; i < 4; i++) {
        int m = mt + ty * 4 + i;
        float4 o = {acc[i][0], acc[i][1], acc[i][2], acc[i][3]};
        *(float4*)(g_Y + (size_t)(b * T_ + m) * C_ + h * DH_ + tx * 4) = o;
    }
}

// ---------------------------------------------------------------------------
extern "C" void kernel_launch(void* const* d_in, const int* in_sizes, int n_in,
                              void* d_out, int out_size)
{
    const float* x    = (const float*)d_in[0];
    const float* src  = (const float*)d_in[1];
    const float* fmap = (const float*)d_in[2];
    const float* bmap = (const float*)d_in[3];
    const float* Wq   = (const float*)d_in[4];
    const float* bq   = (const float*)d_in[5];
    const float* Wk   = (const float*)d_in[6];
    const float* bk   = (const float*)d_in[7];
    const float* Wv   = (const float*)d_in[8];
    const float* bv   = (const float*)d_in[9];
    const float* Wp   = (const float*)d_in[10];
    const float* bp   = (const float*)d_in[11];
    float* out = (float*)d_out;

    float *Qb, *Kb, *Vb, *Yb;
    cudaGetSymbolAddress((void**)&Qb, g_Q);
    cudaGetSymbolAddress((void**)&Kb, g_K);
    cudaGetSymbolAddress((void**)&Vb, g_V);
    cudaGetSymbolAddress((void**)&Yb, g_Y);

    const int M = B_ * T_;                 // 4096
    dim3 gProj(C_ / 128, M / 128);         // 8 x 32

    sgemm_abt<<<gProj, 256>>>(x,   Wq, bq, Qb, M, C_, C_);
    sgemm_abt<<<gProj, 256>>>(src, Wk, bk, Kb, M, C_, C_);
    sgemm_abt<<<gProj, 256>>>(src, Wv, bv, Vb, M, C_, C_);

    dim3 gQK(T_ / 64, T_ / 64, B_ * NH_);  // 8 x 8 x 128
    qk_kernel<<<gQK, 256>>>(fmap, bmap);

    softmax512<<<B_ * NH_ * T_, 128>>>();  // 65536 blocks

    dim3 gAV(T_ / 64, B_ * NH_);           // 8 x 128
    av_kernel<<<gAV, 256>>>();

    sgemm_abt<<<gProj, 256>>>(Yb, Wp, bp, out, M, C_, C_);
}

// round 3
// speedup vs baseline: 2.2786x; 2.2786x over previous
#include <cuda_runtime.h>

#define B_  8
#define T_  512
#define C_  1024
#define NH_ 16
#define DH_ 64
#define HW_ 256

__device__ float g_Q[B_ * T_ * C_];
__device__ float g_K[B_ * T_ * C_];
__device__ float g_V[B_ * T_ * C_];
__device__ float g_Y[B_ * T_ * C_];
__device__ float g_Att[(size_t)B_ * NH_ * T_ * T_];

__device__ __forceinline__ unsigned f2tf(float f) {
    unsigned u;
    asm("cvt.rna.tf32.f32 %0, %1;" : "=r"(u) : "f"(f));
    return u;
}

__device__ __forceinline__ void mma_tf32(float* c, const unsigned* a, const unsigned* b) {
    asm volatile(
        "mma.sync.aligned.m16n8k8.row.col.f32.tf32.tf32.f32 "
        "{%0,%1,%2,%3},{%4,%5,%6,%7},{%8,%9},{%0,%1,%2,%3};"
        : "+f"(c[0]), "+f"(c[1]), "+f"(c[2]), "+f"(c[3])
        : "r"(a[0]), "r"(a[1]), "r"(a[2]), "r"(a[3]), "r"(b[0]), "r"(b[1]));
}

// ---------------------------------------------------------------------------
// C[m,n] = sum_k A[m,k]*W[n,k] + bias[n].  128x128x32 tiles, tf32 MMA.
// ---------------------------------------------------------------------------
__global__ __launch_bounds__(256) void gemm_tf32_abt(
    const float* __restrict__ A, const float* __restrict__ W,
    const float* __restrict__ bias, float* __restrict__ Cmat,
    int M, int N, int K)
{
    __shared__ unsigned As[128][36];
    __shared__ unsigned Bs[128][36];
    const int tid = threadIdx.x, lane = tid & 31, warp = tid >> 5;
    const int wm0 = (warp >> 2) * 64, wn0 = (warp & 3) * 32;
    const int g = lane >> 2, tg = lane & 3;
    const int m0 = blockIdx.y * 128, n0 = blockIdx.x * 128;

    float acc[4][4][4] = {};

    for (int k0 = 0; k0 < K; k0 += 32) {
#pragma unroll
        for (int it = 0; it < 4; it++) {
            int task = tid + it * 256;
            int row = task >> 3, cg = (task & 7) << 2;
            float4 a = *(const float4*)(A + (size_t)(m0 + row) * K + k0 + cg);
            uint4 ua = {f2tf(a.x), f2tf(a.y), f2tf(a.z), f2tf(a.w)};
            *(uint4*)&As[row][cg] = ua;
            float4 w = *(const float4*)(W + (size_t)(n0 + row) * K + k0 + cg);
            uint4 uw = {f2tf(w.x), f2tf(w.y), f2tf(w.z), f2tf(w.w)};
            *(uint4*)&Bs[row][cg] = uw;
        }
        __syncthreads();
#pragma unroll
        for (int ks = 0; ks < 4; ks++) {
            const int c = ks * 8;
            unsigned af[4][4], bf[4][2];
#pragma unroll
            for (int mi = 0; mi < 4; mi++) {
                int r = wm0 + mi * 16;
                af[mi][0] = As[r + g][c + tg];
                af[mi][1] = As[r + g + 8][c + tg];
                af[mi][2] = As[r + g][c + tg + 4];
                af[mi][3] = As[r + g + 8][c + tg + 4];
            }
#pragma unroll
            for (int ni = 0; ni < 4; ni++) {
                int n = wn0 + ni * 8 + g;
                bf[ni][0] = Bs[n][c + tg];
                bf[ni][1] = Bs[n][c + tg + 4];
            }
#pragma unroll
            for (int mi = 0; mi < 4; mi++)
#pragma unroll
                for (int ni = 0; ni < 4; ni++)
                    mma_tf32(acc[mi][ni], af[mi], bf[ni]);
        }
        __syncthreads();
    }

#pragma unroll
    for (int mi = 0; mi < 4; mi++) {
#pragma unroll
        for (int ni = 0; ni < 4; ni++) {
            int row = m0 + wm0 + mi * 16 + g;
            int col = n0 + wn0 + ni * 8 + 2 * tg;
            float b0 = bias[col], b1 = bias[col + 1];
            float2 o0 = {acc[mi][ni][0] + b0, acc[mi][ni][1] + b1};
            float2 o1 = {acc[mi][ni][2] + b0, acc[mi][ni][3] + b1};
            *(float2*)&Cmat[(size_t)row * N + col] = o0;
            *(float2*)&Cmat[(size_t)(row + 8) * N + col] = o1;
        }
    }
}

// ---------------------------------------------------------------------------
// Att[bh,q,k] = 0.125 * Q.K^T with epipolar mask.  128x128 tile, Kdim=64.
// ---------------------------------------------------------------------------
__global__ __launch_bounds__(256) void qk_tf32(const float* __restrict__ fmap,
                                               const float* __restrict__ bmap)
{
    const int bh = blockIdx.z, b = bh >> 4, h = bh & 15;
    const float* Qp = g_Q + (size_t)b * T_ * C_ + h * DH_;
    const float* Kp = g_K + (size_t)b * T_ * C_ + h * DH_;
    const int mt = blockIdx.y * 128, nt = blockIdx.x * 128;
    __shared__ unsigned As[128][36];
    __shared__ unsigned Bs[128][36];
    const int tid = threadIdx.x, lane = tid & 31, warp = tid >> 5;
    const int wm0 = (warp >> 2) * 64, wn0 = (warp & 3) * 32;
    const int g = lane >> 2, tg = lane & 3;

    float acc[4][4][4] = {};

    for (int k0 = 0; k0 < DH_; k0 += 32) {
#pragma unroll
        for (int it = 0; it < 4; it++) {
            int task = tid + it * 256;
            int row = task >> 3, cg = (task & 7) << 2;
            float4 a = *(const float4*)(Qp + (size_t)(mt + row) * C_ + k0 + cg);
            uint4 ua = {f2tf(a.x), f2tf(a.y), f2tf(a.z), f2tf(a.w)};
            *(uint4*)&As[row][cg] = ua;
            float4 w = *(const float4*)(Kp + (size_t)(nt + row) * C_ + k0 + cg);
            uint4 uw = {f2tf(w.x), f2tf(w.y), f2tf(w.z), f2tf(w.w)};
            *(uint4*)&Bs[row][cg] = uw;
        }
        __syncthreads();
#pragma unroll
        for (int ks = 0; ks < 4; ks++) {
            const int c = ks * 8;
            unsigned af[4][4], bf[4][2];
#pragma unroll
            for (int mi = 0; mi < 4; mi++) {
                int r = wm0 + mi * 16;
                af[mi][0] = As[r + g][c + tg];
                af[mi][1] = As[r + g + 8][c + tg];
                af[mi][2] = As[r + g][c + tg + 4];
                af[mi][3] = As[r + g + 8][c + tg + 4];
            }
#pragma unroll
            for (int ni = 0; ni < 4; ni++) {
                int n = wn0 + ni * 8 + g;
                bf[ni][0] = Bs[n][c + tg];
                bf[ni][1] = Bs[n][c + tg + 4];
            }
#pragma unroll
            for (int mi = 0; mi < 4; mi++)
#pragma unroll
                for (int ni = 0; ni < 4; ni++)
                    mma_tf32(acc[mi][ni], af[mi], bf[ni]);
        }
        __syncthreads();
    }

    float* outp = g_Att + (size_t)bh * T_ * T_;
#pragma unroll
    for (int mi = 0; mi < 4; mi++) {
#pragma unroll
        for (int ni = 0; ni < 4; ni++) {
            int kg = nt + wn0 + ni * 8 + 2 * tg;
#pragma unroll
            for (int half = 0; half < 2; half++) {
                int qg = mt + wm0 + mi * 16 + g + half * 8;
                float v0 = acc[mi][ni][half * 2 + 0] * 0.125f;
                float v1 = acc[mi][ni][half * 2 + 1] * 0.125f;
                if (qg < HW_) {
                    if (kg < HW_)
                        v0 *= fmap[((size_t)b * HW_ + qg) * HW_ + kg] *
                              bmap[((size_t)b * HW_ + kg) * HW_ + qg];
                    if (kg + 1 < HW_)
                        v1 *= fmap[((size_t)b * HW_ + qg) * HW_ + kg + 1] *
                              bmap[((size_t)b * HW_ + kg + 1) * HW_ + qg];
                }
                float2 o = {v0, v1};
                *(float2*)&outp[(size_t)qg * T_ + kg] = o;
            }
        }
    }
}

// ---------------------------------------------------------------------------
// In-place softmax over rows of length 512. One block (128 threads) per row.
// ---------------------------------------------------------------------------
__global__ __launch_bounds__(128) void softmax512()
{
    __shared__ float red[4];
    const size_t row = blockIdx.x;
    float4* p = reinterpret_cast<float4*>(g_Att + row * T_);
    float4 v = p[threadIdx.x];
    const int lane = threadIdx.x & 31, w = threadIdx.x >> 5;

    float m = fmaxf(fmaxf(v.x, v.y), fmaxf(v.z, v.w));
#pragma unroll
    for (int o = 16; o > 0; o >>= 1) m = fmaxf(m, __shfl_xor_sync(0xffffffffu, m, o));
    if (lane == 0) red[w] = m;
    __syncthreads();
    m = fmaxf(fmaxf(red[0], red[1]), fmaxf(red[2], red[3]));
    __syncthreads();

    v.x = __expf(v.x - m); v.y = __expf(v.y - m);
    v.z = __expf(v.z - m); v.w = __expf(v.w - m);
    float s = v.x + v.y + v.z + v.w;
#pragma unroll
    for (int o = 16; o > 0; o >>= 1) s += __shfl_xor_sync(0xffffffffu, s, o);
    if (lane == 0) red[w] = s;
    __syncthreads();
    s = red[0] + red[1] + red[2] + red[3];

    float inv = 1.0f / s;
    v.x *= inv; v.y *= inv; v.z *= inv; v.w *= inv;
    p[threadIdx.x] = v;
}

// ---------------------------------------------------------------------------
// Y[b,q,h*64+d] = sum_k Att[bh,q,k]*V[b,k,h*64+d].  128x64 tile, Kdim=512.
// Warps 4x2, warp tile 32x32 (2 m16 x 4 n8).
// ---------------------------------------------------------------------------
__global__ __launch_bounds__(256) void av_tf32()
{
    const int bh = blockIdx.y, b = bh >> 4, h = bh & 15;
    const int mt = blockIdx.x * 128;
    const float* Ap = g_Att + (size_t)bh * T_ * T_;
    const float* Vp = g_V + (size_t)b * T_ * C_ + h * DH_;
    __shared__ unsigned As[128][36];
    __shared__ unsigned Vs[32][68];
    const int tid = threadIdx.x, lane = tid & 31, warp = tid >> 5;
    const int wm0 = (warp >> 1) * 32, wn0 = (warp & 1) * 32;
    const int g = lane >> 2, tg = lane & 3;

    float acc[2][4][4] = {};

    for (int k0 = 0; k0 < T_; k0 += 32) {
#pragma unroll
        for (int it = 0; it < 4; it++) {
            int task = tid + it * 256;
            int row = task >> 3, cg = (task & 7) << 2;
            float4 a = *(const float4*)(Ap + (size_t)(mt + row) * T_ + k0 + cg);
            uint4 ua = {f2tf(a.x), f2tf(a.y), f2tf(a.z), f2tf(a.w)};
            *(uint4*)&As[row][cg] = ua;
        }
#pragma unroll
        for (int it = 0; it < 2; it++) {
            int t2 = tid + it * 256;
            int k = t2 >> 4, dg = (t2 & 15) << 2;
            float4 v = *(const float4*)(Vp + (size_t)(k0 + k) * C_ + dg);
            uint4 uv = {f2tf(v.x), f2tf(v.y), f2tf(v.z), f2tf(v.w)};
            *(uint4*)&Vs[k][dg] = uv;
        }
        __syncthreads();
#pragma unroll
        for (int ks = 0; ks < 4; ks++) {
            const int c = ks * 8;
            unsigned af[2][4], bf[4][2];
#pragma unroll
            for (int mi = 0; mi < 2; mi++) {
                int r = wm0 + mi * 16;
                af[mi][0] = As[r + g][c + tg];
                af[mi][1] = As[r + g + 8][c + tg];
                af[mi][2] = As[r + g][c + tg + 4];
                af[mi][3] = As[r + g + 8][c + tg + 4];
            }
#pragma unroll
            for (int ni = 0; ni < 4; ni++) {
                int n = wn0 + ni * 8 + g;
                bf[ni][0] = Vs[c + tg][n];
                bf[ni][1] = Vs[c + tg + 4][n];
            }
#pragma unroll
            for (int mi = 0; mi < 2; mi++)
#pragma unroll
                for (int ni = 0; ni < 4; ni++)
                    mma_tf32(acc[mi][ni], af[mi], bf[ni]);
        }
        __syncthreads();
    }

#pragma unroll
    for (int mi = 0; mi < 2; mi++) {
#pragma unroll
        for (int ni = 0; ni < 4; ni++) {
            int qg = mt + wm0 + mi * 16 + g;
            int d = wn0 + ni * 8 + 2 * tg;
            float* yp = g_Y + (size_t)(b * T_ + qg) * C_ + h * DH_ + d;
            float2 o0 = {acc[mi][ni][0], acc[mi][ni][1]};
            float2 o1 = {acc[mi][ni][2], acc[mi][ni][3]};
            *(float2*)yp = o0;
            *(float2*)(yp + (size_t)8 * C_) = o1;
        }
    }
}

// ---------------------------------------------------------------------------
extern "C" void kernel_launch(void* const* d_in, const int* in_sizes, int n_in,
                              void* d_out, int out_size)
{
    const float* x    = (const float*)d_in[0];
    const float* src  = (const float*)d_in[1];
    const float* fmap = (const float*)d_in[2];
    const float* bmap = (const float*)d_in[3];
    const float* Wq   = (const float*)d_in[4];
    const float* bq   = (const float*)d_in[5];
    const float* Wk   = (const float*)d_in[6];
    const float* bk   = (const float*)d_in[7];
    const float* Wv   = (const float*)d_in[8];
    const float* bv   = (const float*)d_in[9];
    const float* Wp   = (const float*)d_in[10];
    const float* bp   = (const float*)d_in[11];
    float* out = (float*)d_out;

    float *Qb, *Kb, *Vb, *Yb;
    cudaGetSymbolAddress((void**)&Qb, g_Q);
    cudaGetSymbolAddress((void**)&Kb, g_K);
    cudaGetSymbolAddress((void**)&Vb, g_V);
    cudaGetSymbolAddress((void**)&Yb, g_Y);

    const int M = B_ * T_;                 // 4096
    dim3 gProj(C_ / 128, M / 128);         // 8 x 32

    gemm_tf32_abt<<<gProj, 256>>>(x,   Wq, bq, Qb, M, C_, C_);
    gemm_tf32_abt<<<gProj, 256>>>(src, Wk, bk, Kb, M, C_, C_);
    gemm_tf32_abt<<<gProj, 256>>>(src, Wv, bv, Vb, M, C_, C_);

    dim3 gQK(T_ / 128, T_ / 128, B_ * NH_); // 4 x 4 x 128
    qk_tf32<<<gQK, 256>>>(fmap, bmap);

    softmax512<<<B_ * NH_ * T_, 128>>>();   // 65536 blocks

    dim3 gAV(T_ / 128, B_ * NH_);           // 4 x 128
    av_tf32<<<gAV, 256>>>();

    gemm_tf32_abt<<<gProj, 256>>>(Yb, Wp, bp, out, M, C_, C_);
}

// round 4
// speedup vs baseline: 2.4598x; 1.0795x over previous
#include <cuda_runtime.h>

#define B_  8
#define T_  512
#define C_  1024
#define NH_ 16
#define DH_ 64
#define HW_ 256

__device__ float g_Q[B_ * T_ * C_];
__device__ float g_K[B_ * T_ * C_];
__device__ float g_V[B_ * T_ * C_];
__device__ float g_Y[B_ * T_ * C_];

__device__ __forceinline__ unsigned f2tf(float f) {
    unsigned u;
    asm("cvt.rna.tf32.f32 %0, %1;" : "=r"(u) : "f"(f));
    return u;
}

__device__ __forceinline__ void mma_tf32(float* c, const unsigned* a, const unsigned* b) {
    asm volatile(
        "mma.sync.aligned.m16n8k8.row.col.f32.tf32.tf32.f32 "
        "{%0,%1,%2,%3},{%4,%5,%6,%7},{%8,%9},{%0,%1,%2,%3};"
        : "+f"(c[0]), "+f"(c[1]), "+f"(c[2]), "+f"(c[3])
        : "r"(a[0]), "r"(a[1]), "r"(a[2]), "r"(a[3]), "r"(b[0]), "r"(b[1]));
}

// ---------------------------------------------------------------------------
// GEMM body: C[m,n] = sum_k A[m,k]*W[n,k] + bias[n].  128x128x32 tiles.
// ---------------------------------------------------------------------------
__device__ __forceinline__ void gemm_body(
    const float* __restrict__ A, const float* __restrict__ W,
    const float* __restrict__ bias, float* __restrict__ Cmat,
    int M, int N, int K, int bx, int by)
{
    __shared__ unsigned As[128][36];
    __shared__ unsigned Bs[128][36];
    const int tid = threadIdx.x, lane = tid & 31, warp = tid >> 5;
    const int wm0 = (warp >> 2) * 64, wn0 = (warp & 3) * 32;
    const int g = lane >> 2, tg = lane & 3;
    const int m0 = by * 128, n0 = bx * 128;

    float acc[4][4][4] = {};

    for (int k0 = 0; k0 < K; k0 += 32) {
#pragma unroll
        for (int it = 0; it < 4; it++) {
            int task = tid + it * 256;
            int row = task >> 3, cg = (task & 7) << 2;
            float4 a = *(const float4*)(A + (size_t)(m0 + row) * K + k0 + cg);
            uint4 ua = {f2tf(a.x), f2tf(a.y), f2tf(a.z), f2tf(a.w)};
            *(uint4*)&As[row][cg] = ua;
            float4 w = *(const float4*)(W + (size_t)(n0 + row) * K + k0 + cg);
            uint4 uw = {f2tf(w.x), f2tf(w.y), f2tf(w.z), f2tf(w.w)};
            *(uint4*)&Bs[row][cg] = uw;
        }
        __syncthreads();
#pragma unroll
        for (int ks = 0; ks < 4; ks++) {
            const int c = ks * 8;
            unsigned af[4][4], bf[4][2];
#pragma unroll
            for (int mi = 0; mi < 4; mi++) {
                int r = wm0 + mi * 16;
                af[mi][0] = As[r + g][c + tg];
                af[mi][1] = As[r + g + 8][c + tg];
                af[mi][2] = As[r + g][c + tg + 4];
                af[mi][3] = As[r + g + 8][c + tg + 4];
            }
#pragma unroll
            for (int ni = 0; ni < 4; ni++) {
                int n = wn0 + ni * 8 + g;
                bf[ni][0] = Bs[n][c + tg];
                bf[ni][1] = Bs[n][c + tg + 4];
            }
#pragma unroll
            for (int mi = 0; mi < 4; mi++)
#pragma unroll
                for (int ni = 0; ni < 4; ni++)
                    mma_tf32(acc[mi][ni], af[mi], bf[ni]);
        }
        __syncthreads();
    }

#pragma unroll
    for (int mi = 0; mi < 4; mi++) {
#pragma unroll
        for (int ni = 0; ni < 4; ni++) {
            int row = m0 + wm0 + mi * 16 + g;
            int col = n0 + wn0 + ni * 8 + 2 * tg;
            float b0 = bias[col], b1 = bias[col + 1];
            float2 o0 = {acc[mi][ni][0] + b0, acc[mi][ni][1] + b1};
            float2 o1 = {acc[mi][ni][2] + b0, acc[mi][ni][3] + b1};
            *(float2*)&Cmat[(size_t)row * N + col] = o0;
            *(float2*)&Cmat[(size_t)(row + 8) * N + col] = o1;
        }
    }
}

// Batched QKV projection: blockIdx.z selects (A, W, bias, out) triple.
__global__ __launch_bounds__(256) void gemm_qkv(
    const float* __restrict__ x, const float* __restrict__ src,
    const float* __restrict__ Wq, const float* __restrict__ Wk,
    const float* __restrict__ Wv,
    const float* __restrict__ bq, const float* __restrict__ bk,
    const float* __restrict__ bv)
{
    const int z = blockIdx.z;
    const float* A = (z == 0) ? x : src;
    const float* W = (z == 0) ? Wq : (z == 1) ? Wk : Wv;
    const float* bias = (z == 0) ? bq : (z == 1) ? bk : bv;
    float* out = (z == 0) ? g_Q : (z == 1) ? g_K : g_V;
    gemm_body(A, W, bias, out, B_ * T_, C_, C_, blockIdx.x, blockIdx.y);
}

__global__ __launch_bounds__(256) void gemm_out(
    const float* __restrict__ bias, float* __restrict__ Cmat,
    const float* __restrict__ Wp)
{
    gemm_body(g_Y, Wp, bias, Cmat, B_ * T_, C_, C_, blockIdx.x, blockIdx.y);
}

// ---------------------------------------------------------------------------
// Fused attention: per CTA, 64 q-rows x full 512 k.
//   Phase 1: S = 0.125 * Q K^T  (+ epipolar mask) -> smem (fp32)
//   Phase 2: row softmax in smem, renormalized values stored as tf32 bits
//   Phase 3: O = A V -> g_Y
// Dynamic smem: Ss[64][516] fp32 | Qs[64][68] tf32 | KVs[128][68] tf32
// ---------------------------------------------------------------------------
#define SS_PAD 516
#define ATTN_SMEM (64 * SS_PAD * 4 + 64 * 68 * 4 + 128 * 68 * 4)

__global__ __launch_bounds__(256) void attn_fused(const float* __restrict__ fmap,
                                                  const float* __restrict__ bmap)
{
    extern __shared__ char smraw[];
    float (*Ss)[SS_PAD] = (float (*)[SS_PAD])smraw;
    unsigned (*Ssu)[SS_PAD] = (unsigned (*)[SS_PAD])smraw;
    unsigned (*Qs)[68] = (unsigned (*)[68])(smraw + 64 * SS_PAD * 4);
    unsigned (*KVs)[68] = (unsigned (*)[68])(smraw + 64 * SS_PAD * 4 + 64 * 68 * 4);

    const int bh = blockIdx.y, b = bh >> 4, h = bh & 15;
    const int mt = blockIdx.x * 64;
    const float* Qp = g_Q + (size_t)b * T_ * C_ + h * DH_;
    const float* Kp = g_K + (size_t)b * T_ * C_ + h * DH_;
    const float* Vp = g_V + (size_t)b * T_ * C_ + h * DH_;
    const int tid = threadIdx.x, lane = tid & 31, warp = tid >> 5;
    const int g = lane >> 2, tg = lane & 3;

    // Load Q tile 64x64 -> tf32 smem
#pragma unroll
    for (int it = 0; it < 4; it++) {
        int task = tid + it * 256;
        int row = task >> 4, c4 = (task & 15) << 2;
        float4 q = *(const float4*)(Qp + (size_t)(mt + row) * C_ + c4);
        uint4 u = {f2tf(q.x), f2tf(q.y), f2tf(q.z), f2tf(q.w)};
        *(uint4*)&Qs[row][c4] = u;
    }

    // ---------------- Phase 1: scores ----------------
    {
        const int wm0 = (warp >> 2) * 32, wn0 = (warp & 3) * 32;
        for (int nt = 0; nt < T_; nt += 128) {
            __syncthreads();
#pragma unroll
            for (int it = 0; it < 8; it++) {
                int task = tid + it * 256;
                int row = task >> 4, c4 = (task & 15) << 2;
                float4 kv = *(const float4*)(Kp + (size_t)(nt + row) * C_ + c4);
                uint4 u = {f2tf(kv.x), f2tf(kv.y), f2tf(kv.z), f2tf(kv.w)};
                *(uint4*)&KVs[row][c4] = u;
            }
            __syncthreads();

            float acc[2][4][4] = {};
#pragma unroll
            for (int ks = 0; ks < 8; ks++) {
                const int c = ks * 8;
                unsigned af[2][4], bf[4][2];
#pragma unroll
                for (int mi = 0; mi < 2; mi++) {
                    int r = wm0 + mi * 16;
                    af[mi][0] = Qs[r + g][c + tg];
                    af[mi][1] = Qs[r + g + 8][c + tg];
                    af[mi][2] = Qs[r + g][c + tg + 4];
                    af[mi][3] = Qs[r + g + 8][c + tg + 4];
                }
#pragma unroll
                for (int ni = 0; ni < 4; ni++) {
                    int n = wn0 + ni * 8 + g;
                    bf[ni][0] = KVs[n][c + tg];
                    bf[ni][1] = KVs[n][c + tg + 4];
                }
#pragma unroll
                for (int mi = 0; mi < 2; mi++)
#pragma unroll
                    for (int ni = 0; ni < 4; ni++)
                        mma_tf32(acc[mi][ni], af[mi], bf[ni]);
            }

            // epilogue: scale + mask -> Ss
#pragma unroll
            for (int mi = 0; mi < 2; mi++) {
#pragma unroll
                for (int ni = 0; ni < 4; ni++) {
                    int klo = wn0 + ni * 8 + 2 * tg;
                    int kg = nt + klo;
#pragma unroll
                    for (int half = 0; half < 2; half++) {
                        int qlo = wm0 + mi * 16 + g + half * 8;
                        int qg = mt + qlo;
                        float v0 = acc[mi][ni][half * 2 + 0] * 0.125f;
                        float v1 = acc[mi][ni][half * 2 + 1] * 0.125f;
                        if (qg < HW_) {
                            if (kg < HW_)
                                v0 *= fmap[((size_t)b * HW_ + qg) * HW_ + kg] *
                                      bmap[((size_t)b * HW_ + kg) * HW_ + qg];
                            if (kg + 1 < HW_)
                                v1 *= fmap[((size_t)b * HW_ + qg) * HW_ + kg + 1] *
                                      bmap[((size_t)b * HW_ + kg + 1) * HW_ + qg];
                        }
                        Ss[qlo][kg] = v0;
                        Ss[qlo][kg + 1] = v1;
                    }
                }
            }
        }
    }
    __syncthreads();

    // ---------------- Phase 2: softmax (tf32 out) ----------------
    {
        int row = warp * 8;
#pragma unroll 1
        for (int r = 0; r < 8; r++, row++) {
            float v[16];
            float m = -1e30f;
#pragma unroll
            for (int j = 0; j < 16; j++) {
                v[j] = Ss[row][lane + 32 * j];
                m = fmaxf(m, v[j]);
            }
#pragma unroll
            for (int o = 16; o > 0; o >>= 1)
                m = fmaxf(m, __shfl_xor_sync(0xffffffffu, m, o));
            float s = 0.f;
#pragma unroll
            for (int j = 0; j < 16; j++) {
                v[j] = __expf(v[j] - m);
                s += v[j];
            }
#pragma unroll
            for (int o = 16; o > 0; o >>= 1)
                s += __shfl_xor_sync(0xffffffffu, s, o);
            float inv = 1.0f / s;
#pragma unroll
            for (int j = 0; j < 16; j++)
                Ssu[row][lane + 32 * j] = f2tf(v[j] * inv);
        }
    }
    __syncthreads();

    // ---------------- Phase 3: O = A V ----------------
    {
        const int wm0 = (warp >> 1) * 16, wn0 = (warp & 1) * 32;
        float acc[4][4] = {};
        for (int nt = 0; nt < T_; nt += 128) {
#pragma unroll
            for (int it = 0; it < 8; it++) {
                int task = tid + it * 256;
                int row = task >> 4, c4 = (task & 15) << 2;
                float4 v = *(const float4*)(Vp + (size_t)(nt + row) * C_ + c4);
                uint4 u = {f2tf(v.x), f2tf(v.y), f2tf(v.z), f2tf(v.w)};
                *(uint4*)&KVs[row][c4] = u;
            }
            __syncthreads();
#pragma unroll
            for (int ks = 0; ks < 16; ks++) {
                const int c = ks * 8;
                unsigned af[4], bf[4][2];
                af[0] = Ssu[wm0 + g][nt + c + tg];
                af[1] = Ssu[wm0 + g + 8][nt + c + tg];
                af[2] = Ssu[wm0 + g][nt + c + tg + 4];
                af[3] = Ssu[wm0 + g + 8][nt + c + tg + 4];
#pragma unroll
                for (int ni = 0; ni < 4; ni++) {
                    int n = wn0 + ni * 8 + g;
                    bf[ni][0] = KVs[c + tg][n];
                    bf[ni][1] = KVs[c + tg + 4][n];
                }
#pragma unroll
                for (int ni = 0; ni < 4; ni++)
                    mma_tf32(acc[ni], af, bf[ni]);
            }
            __syncthreads();
        }

#pragma unroll
        for (int ni = 0; ni < 4; ni++) {
            int qg = mt + wm0 + g;
            int d = wn0 + ni * 8 + 2 * tg;
            float* yp = g_Y + (size_t)(b * T_ + qg) * C_ + h * DH_ + d;
            float2 o0 = {acc[ni][0], acc[ni][1]};
            float2 o1 = {acc[ni][2], acc[ni][3]};
            *(float2*)yp = o0;
            *(float2*)(yp + (size_t)8 * C_) = o1;
        }
    }
}

// ---------------------------------------------------------------------------
extern "C" void kernel_launch(void* const* d_in, const int* in_sizes, int n_in,
                              void* d_out, int out_size)
{
    const float* x    = (const float*)d_in[0];
    const float* src  = (const float*)d_in[1];
    const float* fmap = (const float*)d_in[2];
    const float* bmap = (const float*)d_in[3];
    const float* Wq   = (const float*)d_in[4];
    const float* bq   = (const float*)d_in[5];
    const float* Wk   = (const float*)d_in[6];
    const float* bk   = (const float*)d_in[7];
    const float* Wv   = (const float*)d_in[8];
    const float* bv   = (const float*)d_in[9];
    const float* Wp   = (const float*)d_in[10];
    const float* bp   = (const float*)d_in[11];
    float* out = (float*)d_out;

    cudaFuncSetAttribute(attn_fused, cudaFuncAttributeMaxDynamicSharedMemorySize,
                         ATTN_SMEM);

    const int M = B_ * T_;                  // 4096
    dim3 gQKV(C_ / 128, M / 128, 3);        // 8 x 32 x 3
    gemm_qkv<<<gQKV, 256>>>(x, src, Wq, Wk, Wv, bq, bk, bv);

    dim3 gAttn(T_ / 64, B_ * NH_);          // 8 x 128
    attn_fused<<<gAttn, 256, ATTN_SMEM>>>(fmap, bmap);

    dim3 gProj(C_ / 128, M / 128);          // 8 x 32
    gemm_out<<<gProj, 256>>>(bp, out, Wp);
}

// round 5
// speedup vs baseline: 2.4601x; 1.0001x over previous
#include <cuda_runtime.h>

#define B_  8
#define T_  512
#define C_  1024
#define NH_ 16
#define DH_ 64
#define HW_ 256

__device__ float g_Q[B_ * T_ * C_];
__device__ float g_K[B_ * T_ * C_];
__device__ float g_V[B_ * T_ * C_];
__device__ float g_Y[B_ * T_ * C_];

__device__ __forceinline__ unsigned f2tf(float f) {
    unsigned u;
    asm("cvt.rna.tf32.f32 %0, %1;" : "=r"(u) : "f"(f));
    return u;
}

__device__ __forceinline__ void mma_tf32(float* c, const unsigned* a, const unsigned* b) {
    asm volatile(
        "mma.sync.aligned.m16n8k8.row.col.f32.tf32.tf32.f32 "
        "{%0,%1,%2,%3},{%4,%5,%6,%7},{%8,%9},{%0,%1,%2,%3};"
        : "+f"(c[0]), "+f"(c[1]), "+f"(c[2]), "+f"(c[3])
        : "r"(a[0]), "r"(a[1]), "r"(a[2]), "r"(a[3]), "r"(b[0]), "r"(b[1]));
}

// ---------------------------------------------------------------------------
// Pipelined GEMM body: C[m,n] = sum_k A[m,k]*W[n,k] + bias[n].
// 128x128x32 tiles, double-buffered smem, register prefetch.
// Dynamic smem: As[2][128][36] | Bs[2][128][36]  (73728 B)
// ---------------------------------------------------------------------------
#define GEMM_SMEM (2 * 128 * 36 * 4 * 2)

__device__ __forceinline__ void gemm_body_pipe(
    const float* __restrict__ A, const float* __restrict__ W,
    const float* __restrict__ bias, float* __restrict__ Cmat,
    int N, int K, int bx, int by)
{
    extern __shared__ char smraw[];
    unsigned (*As)[128][36] = (unsigned (*)[128][36])smraw;
    unsigned (*Bs)[128][36] = (unsigned (*)[128][36])(smraw + 2 * 128 * 36 * 4);

    const int tid = threadIdx.x, lane = tid & 31, warp = tid >> 5;
    const int wm0 = (warp >> 2) * 64, wn0 = (warp & 3) * 32;
    const int g = lane >> 2, tg = lane & 3;
    const int m0 = by * 128, n0 = bx * 128;
    const int lrow = tid >> 3, lcg = (tid & 7) << 2;  // it-step adds 32 rows

    float acc[4][4][4] = {};
    float4 pa[4], pw[4];

    // Prologue: load k-tile 0
#pragma unroll
    for (int it = 0; it < 4; it++) {
        pa[it] = *(const float4*)(A + (size_t)(m0 + lrow + it * 32) * K + lcg);
        pw[it] = *(const float4*)(W + (size_t)(n0 + lrow + it * 32) * K + lcg);
    }
#pragma unroll
    for (int it = 0; it < 4; it++) {
        uint4 ua = {f2tf(pa[it].x), f2tf(pa[it].y), f2tf(pa[it].z), f2tf(pa[it].w)};
        *(uint4*)&As[0][lrow + it * 32][lcg] = ua;
        uint4 uw = {f2tf(pw[it].x), f2tf(pw[it].y), f2tf(pw[it].z), f2tf(pw[it].w)};
        *(uint4*)&Bs[0][lrow + it * 32][lcg] = uw;
    }
    __syncthreads();

    int cur = 0;
    for (int k0 = 0; k0 < K; k0 += 32) {
        const bool has_next = (k0 + 32 < K);
        if (has_next) {
#pragma unroll
            for (int it = 0; it < 4; it++) {
                pa[it] = *(const float4*)(A + (size_t)(m0 + lrow + it * 32) * K + k0 + 32 + lcg);
                pw[it] = *(const float4*)(W + (size_t)(n0 + lrow + it * 32) * K + k0 + 32 + lcg);
            }
        }
#pragma unroll
        for (int ks = 0; ks < 4; ks++) {
            const int c = ks * 8;
            unsigned af[4][4], bf[4][2];
#pragma unroll
            for (int mi = 0; mi < 4; mi++) {
                int r = wm0 + mi * 16;
                af[mi][0] = As[cur][r + g][c + tg];
                af[mi][1] = As[cur][r + g + 8][c + tg];
                af[mi][2] = As[cur][r + g][c + tg + 4];
                af[mi][3] = As[cur][r + g + 8][c + tg + 4];
            }
#pragma unroll
            for (int ni = 0; ni < 4; ni++) {
                int n = wn0 + ni * 8 + g;
                bf[ni][0] = Bs[cur][n][c + tg];
                bf[ni][1] = Bs[cur][n][c + tg + 4];
            }
#pragma unroll
            for (int mi = 0; mi < 4; mi++)
#pragma unroll
                for (int ni = 0; ni < 4; ni++)
                    mma_tf32(acc[mi][ni], af[mi], bf[ni]);
        }
        if (has_next) {
            const int nb = cur ^ 1;
#pragma unroll
            for (int it = 0; it < 4; it++) {
                uint4 ua = {f2tf(pa[it].x), f2tf(pa[it].y), f2tf(pa[it].z), f2tf(pa[it].w)};
                *(uint4*)&As[nb][lrow + it * 32][lcg] = ua;
                uint4 uw = {f2tf(pw[it].x), f2tf(pw[it].y), f2tf(pw[it].z), f2tf(pw[it].w)};
                *(uint4*)&Bs[nb][lrow + it * 32][lcg] = uw;
            }
            __syncthreads();
        }
        cur ^= 1;
    }

#pragma unroll
    for (int mi = 0; mi < 4; mi++) {
#pragma unroll
        for (int ni = 0; ni < 4; ni++) {
            int row = m0 + wm0 + mi * 16 + g;
            int col = n0 + wn0 + ni * 8 + 2 * tg;
            float b0 = bias[col], b1 = bias[col + 1];
            float2 o0 = {acc[mi][ni][0] + b0, acc[mi][ni][1] + b1};
            float2 o1 = {acc[mi][ni][2] + b0, acc[mi][ni][3] + b1};
            *(float2*)&Cmat[(size_t)row * N + col] = o0;
            *(float2*)&Cmat[(size_t)(row + 8) * N + col] = o1;
        }
    }
}

__global__ __launch_bounds__(256) void gemm_qkv(
    const float* __restrict__ x, const float* __restrict__ src,
    const float* __restrict__ Wq, const float* __restrict__ Wk,
    const float* __restrict__ Wv,
    const float* __restrict__ bq, const float* __restrict__ bk,
    const float* __restrict__ bv)
{
    const int z = blockIdx.z;
    const float* A = (z == 0) ? x : src;
    const float* W = (z == 0) ? Wq : (z == 1) ? Wk : Wv;
    const float* bias = (z == 0) ? bq : (z == 1) ? bk : bv;
    float* out = (z == 0) ? g_Q : (z == 1) ? g_K : g_V;
    gemm_body_pipe(A, W, bias, out, C_, C_, blockIdx.x, blockIdx.y);
}

__global__ __launch_bounds__(256) void gemm_out(
    const float* __restrict__ bias, float* __restrict__ Cmat,
    const float* __restrict__ Wp)
{
    gemm_body_pipe(g_Y, Wp, bias, Cmat, C_, C_, blockIdx.x, blockIdx.y);
}

// ---------------------------------------------------------------------------
// Fused attention, pipelined. Per CTA: 64 q-rows x full 512 k.
// smem: Ss[64][516] fp32 | Qs[64][68] tf32 | KV[2][128][68] tf32  (219136 B)
// ---------------------------------------------------------------------------
#define SS_PAD 516
#define ATTN_SMEM (64 * SS_PAD * 4 + 64 * 68 * 4 + 2 * 128 * 68 * 4)

__global__ __launch_bounds__(256) void attn_fused(const float* __restrict__ fmap,
                                                  const float* __restrict__ bmap)
{
    extern __shared__ char smraw[];
    float (*Ss)[SS_PAD] = (float (*)[SS_PAD])smraw;
    unsigned (*Ssu)[SS_PAD] = (unsigned (*)[SS_PAD])smraw;
    unsigned (*Qs)[68] = (unsigned (*)[68])(smraw + 64 * SS_PAD * 4);
    unsigned (*KV)[128][68] =
        (unsigned (*)[128][68])(smraw + 64 * SS_PAD * 4 + 64 * 68 * 4);

    const int bh = blockIdx.y, b = bh >> 4, h = bh & 15;
    const int mt = blockIdx.x * 64;
    const float* Qp = g_Q + (size_t)b * T_ * C_ + h * DH_;
    const float* Kp = g_K + (size_t)b * T_ * C_ + h * DH_;
    const float* Vp = g_V + (size_t)b * T_ * C_ + h * DH_;
    const int tid = threadIdx.x, lane = tid & 31, warp = tid >> 5;
    const int g = lane >> 2, tg = lane & 3;
    const int krow = tid >> 4, kc4 = (tid & 15) << 2;  // chunk loads: +16 rows/it

    float4 pk[8];

    // Prologue: K chunk 0 prefetch + Q tile load
#pragma unroll
    for (int it = 0; it < 8; it++)
        pk[it] = *(const float4*)(Kp + (size_t)(krow + it * 16) * C_ + kc4);
#pragma unroll
    for (int it = 0; it < 4; it++) {
        int task = tid + it * 256;
        int row = task >> 4, c4 = (task & 15) << 2;
        float4 q = *(const float4*)(Qp + (size_t)(mt + row) * C_ + c4);
        uint4 u = {f2tf(q.x), f2tf(q.y), f2tf(q.z), f2tf(q.w)};
        *(uint4*)&Qs[row][c4] = u;
    }
#pragma unroll
    for (int it = 0; it < 8; it++) {
        uint4 u = {f2tf(pk[it].x), f2tf(pk[it].y), f2tf(pk[it].z), f2tf(pk[it].w)};
        *(uint4*)&KV[0][krow + it * 16][kc4] = u;
    }
    __syncthreads();

    // ---------------- Phase 1: scores ----------------
    {
        const int wm0 = (warp >> 2) * 32, wn0 = (warp & 3) * 32;
        for (int ci = 0; ci < 4; ci++) {
            const int nt = ci * 128;
            const bool has_next = (ci < 3);
            if (has_next) {
#pragma unroll
                for (int it = 0; it < 8; it++)
                    pk[it] = *(const float4*)(Kp + (size_t)(nt + 128 + krow + it * 16) * C_ + kc4);
            }

            float acc[2][4][4] = {};
#pragma unroll
            for (int ks = 0; ks < 8; ks++) {
                const int c = ks * 8;
                unsigned af[2][4], bf[4][2];
#pragma unroll
                for (int mi = 0; mi < 2; mi++) {
                    int r = wm0 + mi * 16;
                    af[mi][0] = Qs[r + g][c + tg];
                    af[mi][1] = Qs[r + g + 8][c + tg];
                    af[mi][2] = Qs[r + g][c + tg + 4];
                    af[mi][3] = Qs[r + g + 8][c + tg + 4];
                }
#pragma unroll
                for (int ni = 0; ni < 4; ni++) {
                    int n = wn0 + ni * 8 + g;
                    bf[ni][0] = KV[ci & 1][n][c + tg];
                    bf[ni][1] = KV[ci & 1][n][c + tg + 4];
                }
#pragma unroll
                for (int mi = 0; mi < 2; mi++)
#pragma unroll
                    for (int ni = 0; ni < 4; ni++)
                        mma_tf32(acc[mi][ni], af[mi], bf[ni]);
            }

            // epilogue: scale + mask -> Ss
#pragma unroll
            for (int mi = 0; mi < 2; mi++) {
#pragma unroll
                for (int ni = 0; ni < 4; ni++) {
                    int klo = wn0 + ni * 8 + 2 * tg;
                    int kg = nt + klo;
#pragma unroll
                    for (int half = 0; half < 2; half++) {
                        int qlo = wm0 + mi * 16 + g + half * 8;
                        int qg = mt + qlo;
                        float v0 = acc[mi][ni][half * 2 + 0] * 0.125f;
                        float v1 = acc[mi][ni][half * 2 + 1] * 0.125f;
                        if (qg < HW_) {
                            if (kg < HW_)
                                v0 *= fmap[((size_t)b * HW_ + qg) * HW_ + kg] *
                                      bmap[((size_t)b * HW_ + kg) * HW_ + qg];
                            if (kg + 1 < HW_)
                                v1 *= fmap[((size_t)b * HW_ + qg) * HW_ + kg + 1] *
                                      bmap[((size_t)b * HW_ + kg + 1) * HW_ + qg];
                        }
                        Ss[qlo][kg] = v0;
                        Ss[qlo][kg + 1] = v1;
                    }
                }
            }

            if (has_next) {
#pragma unroll
                for (int it = 0; it < 8; it++) {
                    uint4 u = {f2tf(pk[it].x), f2tf(pk[it].y), f2tf(pk[it].z), f2tf(pk[it].w)};
                    *(uint4*)&KV[(ci + 1) & 1][krow + it * 16][kc4] = u;
                }
                __syncthreads();
            }
        }
    }
    __syncthreads();

    // ---------------- Phase 2: softmax; prefetch V chunk 0 ----------------
#pragma unroll
    for (int it = 0; it < 8; it++)
        pk[it] = *(const float4*)(Vp + (size_t)(krow + it * 16) * C_ + kc4);
    {
        int row = warp * 8;
#pragma unroll 1
        for (int r = 0; r < 8; r++, row++) {
            float v[16];
            float m = -1e30f;
#pragma unroll
            for (int j = 0; j < 16; j++) {
                v[j] = Ss[row][lane + 32 * j];
                m = fmaxf(m, v[j]);
            }
#pragma unroll
            for (int o = 16; o > 0; o >>= 1)
                m = fmaxf(m, __shfl_xor_sync(0xffffffffu, m, o));
            float s = 0.f;
#pragma unroll
            for (int j = 0; j < 16; j++) {
                v[j] = __expf(v[j] - m);
                s += v[j];
            }
#pragma unroll
            for (int o = 16; o > 0; o >>= 1)
                s += __shfl_xor_sync(0xffffffffu, s, o);
            float inv = 1.0f / s;
#pragma unroll
            for (int j = 0; j < 16; j++)
                Ssu[row][lane + 32 * j] = f2tf(v[j] * inv);
        }
    }
#pragma unroll
    for (int it = 0; it < 8; it++) {
        uint4 u = {f2tf(pk[it].x), f2tf(pk[it].y), f2tf(pk[it].z), f2tf(pk[it].w)};
        *(uint4*)&KV[0][krow + it * 16][kc4] = u;
    }
    __syncthreads();

    // ---------------- Phase 3: O = A V ----------------
    {
        const int wm0 = (warp >> 1) * 16, wn0 = (warp & 1) * 32;
        float acc[4][4] = {};
        for (int ci = 0; ci < 4; ci++) {
            const int nt = ci * 128;
            const bool has_next = (ci < 3);
            if (has_next) {
#pragma unroll
                for (int it = 0; it < 8; it++)
                    pk[it] = *(const float4*)(Vp + (size_t)(nt + 128 + krow + it * 16) * C_ + kc4);
            }
#pragma unroll
            for (int ks = 0; ks < 16; ks++) {
                const int c = ks * 8;
                unsigned af[4], bf[4][2];
                af[0] = Ssu[wm0 + g][nt + c + tg];
                af[1] = Ssu[wm0 + g + 8][nt + c + tg];
                af[2] = Ssu[wm0 + g][nt + c + tg + 4];
                af[3] = Ssu[wm0 + g + 8][nt + c + tg + 4];
#pragma unroll
                for (int ni = 0; ni < 4; ni++) {
                    int n = wn0 + ni * 8 + g;
                    bf[ni][0] = KV[ci & 1][c + tg][n];
                    bf[ni][1] = KV[ci & 1][c + tg + 4][n];
                }
#pragma unroll
                for (int ni = 0; ni < 4; ni++)
                    mma_tf32(acc[ni], af, bf[ni]);
            }
            if (has_next) {
#pragma unroll
                for (int it = 0; it < 8; it++) {
                    uint4 u = {f2tf(pk[it].x), f2tf(pk[it].y), f2tf(pk[it].z), f2tf(pk[it].w)};
                    *(uint4*)&KV[(ci + 1) & 1][krow + it * 16][kc4] = u;
                }
                __syncthreads();
            }
        }

#pragma unroll
        for (int ni = 0; ni < 4; ni++) {
            int qg = mt + wm0 + g;
            int d = wn0 + ni * 8 + 2 * tg;
            float* yp = g_Y + (size_t)(b * T_ + qg) * C_ + h * DH_ + d;
            float2 o0 = {acc[ni][0], acc[ni][1]};
            float2 o1 = {acc[ni][2], acc[ni][3]};
            *(float2*)yp = o0;
            *(float2*)(yp + (size_t)8 * C_) = o1;
        }
    }
}

// ---------------------------------------------------------------------------
extern "C" void kernel_launch(void* const* d_in, const int* in_sizes, int n_in,
                              void* d_out, int out_size)
{
    const float* x    = (const float*)d_in[0];
    const float* src  = (const float*)d_in[1];
    const float* fmap = (const float*)d_in[2];
    const float* bmap = (const float*)d_in[3];
    const float* Wq   = (const float*)d_in[4];
    const float* bq   = (const float*)d_in[5];
    const float* Wk   = (const float*)d_in[6];
    const float* bk   = (const float*)d_in[7];
    const float* Wv   = (const float*)d_in[8];
    const float* bv   = (const float*)d_in[9];
    const float* Wp   = (const float*)d_in[10];
    const float* bp   = (const float*)d_in[11];
    float* out = (float*)d_out;

    cudaFuncSetAttribute(gemm_qkv, cudaFuncAttributeMaxDynamicSharedMemorySize,
                         GEMM_SMEM);
    cudaFuncSetAttribute(gemm_out, cudaFuncAttributeMaxDynamicSharedMemorySize,
                         GEMM_SMEM);
    cudaFuncSetAttribute(attn_fused, cudaFuncAttributeMaxDynamicSharedMemorySize,
                         ATTN_SMEM);

    const int M = B_ * T_;                  // 4096
    dim3 gQKV(C_ / 128, M / 128, 3);        // 8 x 32 x 3
    gemm_qkv<<<gQKV, 256, GEMM_SMEM>>>(x, src, Wq, Wk, Wv, bq, bk, bv);

    dim3 gAttn(T_ / 64, B_ * NH_);          // 8 x 128
    attn_fused<<<gAttn, 256, ATTN_SMEM>>>(fmap, bmap);

    dim3 gProj(C_ / 128, M / 128);          // 8 x 32
    gemm_out<<<gProj, 256, GEMM_SMEM>>>(bp, out, Wp);
}

// round 6
// speedup vs baseline: 2.6430x; 1.0743x over previous
#include <cuda_runtime.h>

#define B_  8
#define T_  512
#define C_  1024
#define NH_ 16
#define DH_ 64
#define HW_ 256

// tf32-bit scratch: [x:4M][src:4M][Wq:1M][Wk:1M][Wv:1M][Wp:1M] u32
#define X_OFF  0u
#define S_OFF  4194304u
#define W_OFF  8388608u
#define W_SZ   1048576u
__device__ unsigned g_TF[12 * 1048576];
__device__ unsigned g_Q[B_ * T_ * C_];   // tf32 bits
__device__ unsigned g_K[B_ * T_ * C_];
__device__ unsigned g_V[B_ * T_ * C_];
__device__ unsigned g_Y[B_ * T_ * C_];

__device__ __forceinline__ unsigned f2tf(float f) {
    unsigned u;
    asm("cvt.rna.tf32.f32 %0, %1;" : "=r"(u) : "f"(f));
    return u;
}

__device__ __forceinline__ void mma_tf32(float* c, const unsigned* a, const unsigned* b) {
    asm volatile(
        "mma.sync.aligned.m16n8k8.row.col.f32.tf32.tf32.f32 "
        "{%0,%1,%2,%3},{%4,%5,%6,%7},{%8,%9},{%0,%1,%2,%3};"
        : "+f"(c[0]), "+f"(c[1]), "+f"(c[2]), "+f"(c[3])
        : "r"(a[0]), "r"(a[1]), "r"(a[2]), "r"(a[3]), "r"(b[0]), "r"(b[1]));
}

__device__ __forceinline__ unsigned smaddr(const void* p) {
    unsigned a;
    asm("{ .reg .u64 t; cvta.to.shared.u64 t, %1; cvt.u32.u64 %0, t; }"
        : "=r"(a) : "l"(p));
    return a;
}
#define CP16(dst, src) \
    asm volatile("cp.async.cg.shared.global [%0], [%1], 16;" :: "r"(dst), "l"(src))
#define CP_COMMIT() asm volatile("cp.async.commit_group;" ::: "memory")
#define CP_WAIT0()  asm volatile("cp.async.wait_group 0;" ::: "memory")

// ---------------------------------------------------------------------------
// Prep: round fp32 -> tf32 bits once (same cvt.rna the GEMMs did in staging).
// ---------------------------------------------------------------------------
__global__ __launch_bounds__(256) void prep_tf32(
    const float4* __restrict__ x, const float4* __restrict__ src,
    const float4* __restrict__ wq, const float4* __restrict__ wk,
    const float4* __restrict__ wv, const float4* __restrict__ wp)
{
    unsigned i = blockIdx.x * 256 + threadIdx.x;  // float4 index, < 3145728
    const float4* s; unsigned off;
    if      (i < 1048576u) { s = x;   off = i; }
    else if (i < 2097152u) { s = src; off = i - 1048576u; }
    else if (i < 2359296u) { s = wq;  off = i - 2097152u; }
    else if (i < 2621440u) { s = wk;  off = i - 2359296u; }
    else if (i < 2883584u) { s = wv;  off = i - 2621440u; }
    else                   { s = wp;  off = i - 2883584u; }
    float4 v = s[off];
    uint4 u = {f2tf(v.x), f2tf(v.y), f2tf(v.z), f2tf(v.w)};
    ((uint4*)g_TF)[i] = u;
}

// ---------------------------------------------------------------------------
// Pipelined GEMM: C[m,n] = sum_k A[m,k]*W[n,k] + bias[n], tf32-bit inputs.
// 128x128x32 tiles, cp.async double buffer. smem: 2x(As+Bs)[128][36] = 73728B
// ---------------------------------------------------------------------------
#define GEMM_SMEM (2 * 128 * 36 * 4 * 2)

template <bool TF32OUT>
__device__ __forceinline__ void gemm_body_cp(
    const unsigned* __restrict__ A, const unsigned* __restrict__ W,
    const float* __restrict__ bias, void* __restrict__ Cmat,
    int N, int K, int bx, int by)
{
    extern __shared__ unsigned smem_u[];
    unsigned (*As)[128][36] = (unsigned (*)[128][36])smem_u;
    unsigned (*Bs)[128][36] = (unsigned (*)[128][36])(smem_u + 2 * 128 * 36);

    const int tid = threadIdx.x, lane = tid & 31, warp = tid >> 5;
    const int wm0 = (warp >> 2) * 64, wn0 = (warp & 3) * 32;
    const int g = lane >> 2, tg = lane & 3;
    const int m0 = by * 128, n0 = bx * 128;
    const int lrow = tid >> 3, lcg = (tid & 7) << 2;

    float acc[4][4][4] = {};

    // prologue: k-tile 0 into buffer 0
#pragma unroll
    for (int it = 0; it < 4; it++) {
        CP16(smaddr(&As[0][lrow + it * 32][lcg]),
             A + (size_t)(m0 + lrow + it * 32) * K + lcg);
        CP16(smaddr(&Bs[0][lrow + it * 32][lcg]),
             W + (size_t)(n0 + lrow + it * 32) * K + lcg);
    }
    CP_COMMIT();
    CP_WAIT0();
    __syncthreads();

    int cur = 0;
    for (int k0 = 0; k0 < K; k0 += 32) {
        const bool has_next = (k0 + 32 < K);
        if (has_next) {
            const int nb = cur ^ 1;
#pragma unroll
            for (int it = 0; it < 4; it++) {
                CP16(smaddr(&As[nb][lrow + it * 32][lcg]),
                     A + (size_t)(m0 + lrow + it * 32) * K + k0 + 32 + lcg);
                CP16(smaddr(&Bs[nb][lrow + it * 32][lcg]),
                     W + (size_t)(n0 + lrow + it * 32) * K + k0 + 32 + lcg);
            }
            CP_COMMIT();
        }
#pragma unroll
        for (int ks = 0; ks < 4; ks++) {
            const int c = ks * 8;
            unsigned af[4][4], bf[4][2];
#pragma unroll
            for (int mi = 0; mi < 4; mi++) {
                int r = wm0 + mi * 16;
                af[mi][0] = As[cur][r + g][c + tg];
                af[mi][1] = As[cur][r + g + 8][c + tg];
                af[mi][2] = As[cur][r + g][c + tg + 4];
                af[mi][3] = As[cur][r + g + 8][c + tg + 4];
            }
#pragma unroll
            for (int ni = 0; ni < 4; ni++) {
                int n = wn0 + ni * 8 + g;
                bf[ni][0] = Bs[cur][n][c + tg];
                bf[ni][1] = Bs[cur][n][c + tg + 4];
            }
#pragma unroll
            for (int mi = 0; mi < 4; mi++)
#pragma unroll
                for (int ni = 0; ni < 4; ni++)
                    mma_tf32(acc[mi][ni], af[mi], bf[ni]);
        }
        if (has_next) {
            CP_WAIT0();
            __syncthreads();
        }
        cur ^= 1;
    }

#pragma unroll
    for (int mi = 0; mi < 4; mi++) {
#pragma unroll
        for (int ni = 0; ni < 4; ni++) {
            int row = m0 + wm0 + mi * 16 + g;
            int col = n0 + wn0 + ni * 8 + 2 * tg;
            float b0 = bias[col], b1 = bias[col + 1];
            if (TF32OUT) {
                unsigned* Cu = (unsigned*)Cmat;
                uint2 o0 = {f2tf(acc[mi][ni][0] + b0), f2tf(acc[mi][ni][1] + b1)};
                uint2 o1 = {f2tf(acc[mi][ni][2] + b0), f2tf(acc[mi][ni][3] + b1)};
                *(uint2*)&Cu[(size_t)row * N + col] = o0;
                *(uint2*)&Cu[(size_t)(row + 8) * N + col] = o1;
            } else {
                float* Cf = (float*)Cmat;
                float2 o0 = {acc[mi][ni][0] + b0, acc[mi][ni][1] + b1};
                float2 o1 = {acc[mi][ni][2] + b0, acc[mi][ni][3] + b1};
                *(float2*)&Cf[(size_t)row * N + col] = o0;
                *(float2*)&Cf[(size_t)(row + 8) * N + col] = o1;
            }
        }
    }
}

__global__ __launch_bounds__(256, 2) void gemm_qkv(
    const float* __restrict__ bq, const float* __restrict__ bk,
    const float* __restrict__ bv)
{
    const int z = blockIdx.z;
    const unsigned* A = g_TF + (z == 0 ? X_OFF : S_OFF);
    const unsigned* W = g_TF + W_OFF + (unsigned)z * W_SZ;
    const float* bias = (z == 0) ? bq : (z == 1) ? bk : bv;
    unsigned* out = (z == 0) ? g_Q : (z == 1) ? g_K : g_V;
    gemm_body_cp<true>(A, W, bias, out, C_, C_, blockIdx.x, blockIdx.y);
}

__global__ __launch_bounds__(256, 2) void gemm_out(
    const float* __restrict__ bias, float* __restrict__ Cmat)
{
    gemm_body_cp<false>(g_Y, g_TF + W_OFF + 3u * W_SZ, bias, Cmat,
                        C_, C_, blockIdx.x, blockIdx.y);
}

// ---------------------------------------------------------------------------
// Fused attention, cp.async pipelined. Per CTA: 64 q-rows x full 512 k.
// smem: Ss[64][516] fp32 | Qs[64][68] | KV[2][128][68]  (219136 B)
// ---------------------------------------------------------------------------
#define SS_PAD 516
#define ATTN_SMEM (64 * SS_PAD * 4 + 64 * 68 * 4 + 2 * 128 * 68 * 4)

__global__ __launch_bounds__(256) void attn_fused(const float* __restrict__ fmap,
                                                  const float* __restrict__ bmap)
{
    extern __shared__ char smraw[];
    float (*Ss)[SS_PAD] = (float (*)[SS_PAD])smraw;
    unsigned (*Ssu)[SS_PAD] = (unsigned (*)[SS_PAD])smraw;
    unsigned (*Qs)[68] = (unsigned (*)[68])(smraw + 64 * SS_PAD * 4);
    unsigned (*KV)[128][68] =
        (unsigned (*)[128][68])(smraw + 64 * SS_PAD * 4 + 64 * 68 * 4);

    const int bh = blockIdx.y, b = bh >> 4, h = bh & 15;
    const int mt = blockIdx.x * 64;
    const unsigned* Qp = g_Q + (size_t)b * T_ * C_ + h * DH_;
    const unsigned* Kp = g_K + (size_t)b * T_ * C_ + h * DH_;
    const unsigned* Vp = g_V + (size_t)b * T_ * C_ + h * DH_;
    const int tid = threadIdx.x, lane = tid & 31, warp = tid >> 5;
    const int g = lane >> 2, tg = lane & 3;
    const int krow = tid >> 4, kc4 = (tid & 15) << 2;

    // prologue: Q tile + K chunk 0, one cp.async group
#pragma unroll
    for (int it = 0; it < 4; it++) {
        int task = tid + it * 256;
        int row = task >> 4, c4 = (task & 15) << 2;
        CP16(smaddr(&Qs[row][c4]), Qp + (size_t)(mt + row) * C_ + c4);
    }
#pragma unroll
    for (int it = 0; it < 8; it++)
        CP16(smaddr(&KV[0][krow + it * 16][kc4]),
             Kp + (size_t)(krow + it * 16) * C_ + kc4);
    CP_COMMIT();
    CP_WAIT0();
    __syncthreads();

    // ---------------- Phase 1: scores ----------------
    {
        const int wm0 = (warp >> 2) * 32, wn0 = (warp & 3) * 32;
        for (int ci = 0; ci < 4; ci++) {
            const int nt = ci * 128;
            const bool has_next = (ci < 3);
            if (has_next) {
#pragma unroll
                for (int it = 0; it < 8; it++)
                    CP16(smaddr(&KV[(ci + 1) & 1][krow + it * 16][kc4]),
                         Kp + (size_t)(nt + 128 + krow + it * 16) * C_ + kc4);
                CP_COMMIT();
            }

            float acc[2][4][4] = {};
#pragma unroll
            for (int ks = 0; ks < 8; ks++) {
                const int c = ks * 8;
                unsigned af[2][4], bf[4][2];
#pragma unroll
                for (int mi = 0; mi < 2; mi++) {
                    int r = wm0 + mi * 16;
                    af[mi][0] = Qs[r + g][c + tg];
                    af[mi][1] = Qs[r + g + 8][c + tg];
                    af[mi][2] = Qs[r + g][c + tg + 4];
                    af[mi][3] = Qs[r + g + 8][c + tg + 4];
                }
#pragma unroll
                for (int ni = 0; ni < 4; ni++) {
                    int n = wn0 + ni * 8 + g;
                    bf[ni][0] = KV[ci & 1][n][c + tg];
                    bf[ni][1] = KV[ci & 1][n][c + tg + 4];
                }
#pragma unroll
                for (int mi = 0; mi < 2; mi++)
#pragma unroll
                    for (int ni = 0; ni < 4; ni++)
                        mma_tf32(acc[mi][ni], af[mi], bf[ni]);
            }

            // epilogue: scale + mask -> Ss
#pragma unroll
            for (int mi = 0; mi < 2; mi++) {
#pragma unroll
                for (int ni = 0; ni < 4; ni++) {
                    int klo = wn0 + ni * 8 + 2 * tg;
                    int kg = nt + klo;
#pragma unroll
                    for (int half = 0; half < 2; half++) {
                        int qlo = wm0 + mi * 16 + g + half * 8;
                        int qg = mt + qlo;
                        float v0 = acc[mi][ni][half * 2 + 0] * 0.125f;
                        float v1 = acc[mi][ni][half * 2 + 1] * 0.125f;
                        if (qg < HW_) {
                            if (kg < HW_)
                                v0 *= fmap[((size_t)b * HW_ + qg) * HW_ + kg] *
                                      bmap[((size_t)b * HW_ + kg) * HW_ + qg];
                            if (kg + 1 < HW_)
                                v1 *= fmap[((size_t)b * HW_ + qg) * HW_ + kg + 1] *
                                      bmap[((size_t)b * HW_ + kg + 1) * HW_ + qg];
                        }
                        Ss[qlo][kg] = v0;
                        Ss[qlo][kg + 1] = v1;
                    }
                }
            }

            if (has_next) {
                CP_WAIT0();
                __syncthreads();
            }
        }
    }
    __syncthreads();

    // ---------------- Phase 2: softmax; async V chunk 0 ----------------
#pragma unroll
    for (int it = 0; it < 8; it++)
        CP16(smaddr(&KV[0][krow + it * 16][kc4]),
             Vp + (size_t)(krow + it * 16) * C_ + kc4);
    CP_COMMIT();
    {
        int row = warp * 8;
#pragma unroll 1
        for (int r = 0; r < 8; r++, row++) {
            float v[16];
            float m = -1e30f;
#pragma unroll
            for (int j = 0; j < 16; j++) {
                v[j] = Ss[row][lane + 32 * j];
                m = fmaxf(m, v[j]);
            }
#pragma unroll
            for (int o = 16; o > 0; o >>= 1)
                m = fmaxf(m, __shfl_xor_sync(0xffffffffu, m, o));
            float s = 0.f;
#pragma unroll
            for (int j = 0; j < 16; j++) {
                v[j] = __expf(v[j] - m);
                s += v[j];
            }
#pragma unroll
            for (int o = 16; o > 0; o >>= 1)
                s += __shfl_xor_sync(0xffffffffu, s, o);
            float inv = 1.0f / s;
#pragma unroll
            for (int j = 0; j < 16; j++)
                Ssu[row][lane + 32 * j] = f2tf(v[j] * inv);
        }
    }
    CP_WAIT0();
    __syncthreads();

    // ---------------- Phase 3: O = A V ----------------
    {
        const int wm0 = (warp >> 1) * 16, wn0 = (warp & 1) * 32;
        float acc[4][4] = {};
        for (int ci = 0; ci < 4; ci++) {
            const int nt = ci * 128;
            const bool has_next = (ci < 3);
            if (has_next) {
#pragma unroll
                for (int it = 0; it < 8; it++)
                    CP16(smaddr(&KV[(ci + 1) & 1][krow + it * 16][kc4]),
                         Vp + (size_t)(nt + 128 + krow + it * 16) * C_ + kc4);
                CP_COMMIT();
            }
#pragma unroll
            for (int ks = 0; ks < 16; ks++) {
                const int c = ks * 8;
                unsigned af[4], bf[4][2];
                af[0] = Ssu[wm0 + g][nt + c + tg];
                af[1] = Ssu[wm0 + g + 8][nt + c + tg];
                af[2] = Ssu[wm0 + g][nt + c + tg + 4];
                af[3] = Ssu[wm0 + g + 8][nt + c + tg + 4];
#pragma unroll
                for (int ni = 0; ni < 4; ni++) {
                    int n = wn0 + ni * 8 + g;
                    bf[ni][0] = KV[ci & 1][c + tg][n];
                    bf[ni][1] = KV[ci & 1][c + tg + 4][n];
                }
#pragma unroll
                for (int ni = 0; ni < 4; ni++)
                    mma_tf32(acc[ni], af, bf[ni]);
            }
            if (has_next) {
                CP_WAIT0();
                __syncthreads();
            }
        }

#pragma unroll
        for (int ni = 0; ni < 4; ni++) {
            int qg = mt + wm0 + g;
            int d = wn0 + ni * 8 + 2 * tg;
            unsigned* yp = g_Y + (size_t)(b * T_ + qg) * C_ + h * DH_ + d;
            uint2 o0 = {f2tf(acc[ni][0]), f2tf(acc[ni][1])};
            uint2 o1 = {f2tf(acc[ni][2]), f2tf(acc[ni][3])};
            *(uint2*)yp = o0;
            *(uint2*)(yp + (size_t)8 * C_) = o1;
        }
    }
}

// ---------------------------------------------------------------------------
extern "C" void kernel_launch(void* const* d_in, const int* in_sizes, int n_in,
                              void* d_out, int out_size)
{
    const float* x    = (const float*)d_in[0];
    const float* src  = (const float*)d_in[1];
    const float* fmap = (const float*)d_in[2];
    const float* bmap = (const float*)d_in[3];
    const float* Wq   = (const float*)d_in[4];
    const float* bq   = (const float*)d_in[5];
    const float* Wk   = (const float*)d_in[6];
    const float* bk   = (const float*)d_in[7];
    const float* Wv   = (const float*)d_in[8];
    const float* bv   = (const float*)d_in[9];
    const float* Wp   = (const float*)d_in[10];
    const float* bp   = (const float*)d_in[11];
    float* out = (float*)d_out;

    cudaFuncSetAttribute(gemm_qkv, cudaFuncAttributeMaxDynamicSharedMemorySize,
                         GEMM_SMEM);
    cudaFuncSetAttribute(gemm_out, cudaFuncAttributeMaxDynamicSharedMemorySize,
                         GEMM_SMEM);
    cudaFuncSetAttribute(attn_fused, cudaFuncAttributeMaxDynamicSharedMemorySize,
                         ATTN_SMEM);

    prep_tf32<<<12288, 256>>>((const float4*)x, (const float4*)src,
                              (const float4*)Wq, (const float4*)Wk,
                              (const float4*)Wv, (const float4*)Wp);

    const int M = B_ * T_;                  // 4096
    dim3 gQKV(C_ / 128, M / 128, 3);        // 8 x 32 x 3
    gemm_qkv<<<gQKV, 256, GEMM_SMEM>>>(bq, bk, bv);

    dim3 gAttn(T_ / 64, B_ * NH_);          // 8 x 128
    attn_fused<<<gAttn, 256, ATTN_SMEM>>>(fmap, bmap);

    dim3 gProj(C_ / 128, M / 128);          // 8 x 32
    gemm_out<<<gProj, 256, GEMM_SMEM>>>(bp, out);
}

// round 9
// speedup vs baseline: 2.6496x; 1.0025x over previous
#include <cuda_runtime.h>
#include <cstdint>

#define B_  8
#define T_  512
#define C_  1024
#define NH_ 16
#define DH_ 64
#define HW_ 256

// tf32-bit scratch: [x:4M][src:4M][Wq:1M][Wk:1M][Wv:1M][Wp:1M] u32
#define X_OFF  0u
#define S_OFF  4194304u
#define W_OFF  8388608u
#define W_SZ   1048576u
__device__ unsigned g_TF[12 * 1048576];
__device__ unsigned g_Q[B_ * T_ * C_];   // tf32 bits
__device__ unsigned g_K[B_ * T_ * C_];
__device__ unsigned g_V[B_ * T_ * C_];
__device__ unsigned g_Y[B_ * T_ * C_];

__device__ __forceinline__ unsigned f2tf(float f) {
    unsigned u;
    asm("cvt.rna.tf32.f32 %0, %1;" : "=r"(u) : "f"(f));
    return u;
}

__device__ __forceinline__ void mma_tf32(float* c, const unsigned* a, const unsigned* b) {
    asm volatile(
        "mma.sync.aligned.m16n8k8.row.col.f32.tf32.tf32.f32 "
        "{%0,%1,%2,%3},{%4,%5,%6,%7},{%8,%9},{%0,%1,%2,%3};"
        : "+f"(c[0]), "+f"(c[1]), "+f"(c[2]), "+f"(c[3])
        : "r"(a[0]), "r"(a[1]), "r"(a[2]), "r"(a[3]), "r"(b[0]), "r"(b[1]));
}

__device__ __forceinline__ unsigned smaddr(const void* p) {
    unsigned a;
    asm("{ .reg .u64 t; cvta.to.shared.u64 t, %1; cvt.u32.u64 %0, t; }"
        : "=r"(a) : "l"(p));
    return a;
}
#define CP16(dst, src) \
    asm volatile("cp.async.cg.shared.global [%0], [%1], 16;" :: "r"(dst), "l"(src))
#define CP_COMMIT() asm volatile("cp.async.commit_group;" ::: "memory")
#define CP_WAIT0()  asm volatile("cp.async.wait_group 0;" ::: "memory")

// ---------------------------------------------------------------------------
// Prep: round fp32 -> tf32 bits once.
// ---------------------------------------------------------------------------
__global__ __launch_bounds__(256) void prep_tf32(
    const float4* __restrict__ x, const float4* __restrict__ src,
    const float4* __restrict__ wq, const float4* __restrict__ wk,
    const float4* __restrict__ wv, const float4* __restrict__ wp)
{
    unsigned i = blockIdx.x * 256 + threadIdx.x;
    const float4* s; unsigned off;
    if      (i < 1048576u) { s = x;   off = i; }
    else if (i < 2097152u) { s = src; off = i - 1048576u; }
    else if (i < 2359296u) { s = wq;  off = i - 2097152u; }
    else if (i < 2621440u) { s = wk;  off = i - 2359296u; }
    else if (i < 2883584u) { s = wv;  off = i - 2621440u; }
    else                   { s = wp;  off = i - 2883584u; }
    float4 v = s[off];
    uint4 u = {f2tf(v.x), f2tf(v.y), f2tf(v.z), f2tf(v.w)};
    ((uint4*)g_TF)[i] = u;
}

// ---------------------------------------------------------------------------
// Pipelined GEMM: C[m,n] = sum_k A[m,k]*W[n,k] + bias[n], tf32-bit inputs.
// 128x128x32 tiles, cp.async double buffer. smem: 2x(As+Bs)[128][36] = 73728B
// ---------------------------------------------------------------------------
#define GEMM_SMEM (2 * 128 * 36 * 4 * 2)

template <bool TF32OUT>
__device__ __forceinline__ void gemm_body_cp(
    const unsigned* __restrict__ A, const unsigned* __restrict__ W,
    const float* __restrict__ bias, void* __restrict__ Cmat,
    int N, int K, int bx, int by)
{
    extern __shared__ unsigned smem_u[];
    unsigned (*As)[128][36] = (unsigned (*)[128][36])smem_u;
    unsigned (*Bs)[128][36] = (unsigned (*)[128][36])(smem_u + 2 * 128 * 36);

    const int tid = threadIdx.x, lane = tid & 31, warp = tid >> 5;
    const int wm0 = (warp >> 2) * 64, wn0 = (warp & 3) * 32;
    const int g = lane >> 2, tg = lane & 3;
    const int m0 = by * 128, n0 = bx * 128;
    const int lrow = tid >> 3, lcg = (tid & 7) << 2;

    float acc[4][4][4] = {};

    // prologue: k-tile 0 into buffer 0
#pragma unroll
    for (int it = 0; it < 4; it++) {
        CP16(smaddr(&As[0][lrow + it * 32][lcg]),
             A + (size_t)(m0 + lrow + it * 32) * K + lcg);
        CP16(smaddr(&Bs[0][lrow + it * 32][lcg]),
             W + (size_t)(n0 + lrow + it * 32) * K + lcg);
    }
    CP_COMMIT();
    CP_WAIT0();
    __syncthreads();

    int cur = 0;
    for (int k0 = 0; k0 < K; k0 += 32) {
        const bool has_next = (k0 + 32 < K);
        if (has_next) {
            const int nb = cur ^ 1;
#pragma unroll
            for (int it = 0; it < 4; it++) {
                CP16(smaddr(&As[nb][lrow + it * 32][lcg]),
                     A + (size_t)(m0 + lrow + it * 32) * K + k0 + 32 + lcg);
                CP16(smaddr(&Bs[nb][lrow + it * 32][lcg]),
                     W + (size_t)(n0 + lrow + it * 32) * K + k0 + 32 + lcg);
            }
            CP_COMMIT();
        }
#pragma unroll
        for (int ks = 0; ks < 4; ks++) {
            const int c = ks * 8;
            unsigned af[4][4], bf[4][2];
#pragma unroll
            for (int mi = 0; mi < 4; mi++) {
                int r = wm0 + mi * 16;
                af[mi][0] = As[cur][r + g][c + tg];
                af[mi][1] = As[cur][r + g + 8][c + tg];
                af[mi][2] = As[cur][r + g][c + tg + 4];
                af[mi][3] = As[cur][r + g + 8][c + tg + 4];
            }
#pragma unroll
            for (int ni = 0; ni < 4; ni++) {
                int n = wn0 + ni * 8 + g;
                bf[ni][0] = Bs[cur][n][c + tg];
                bf[ni][1] = Bs[cur][n][c + tg + 4];
            }
#pragma unroll
            for (int mi = 0; mi < 4; mi++)
#pragma unroll
                for (int ni = 0; ni < 4; ni++)
                    mma_tf32(acc[mi][ni], af[mi], bf[ni]);
        }
        if (has_next) {
            CP_WAIT0();
            __syncthreads();
        }
        cur ^= 1;
    }

#pragma unroll
    for (int mi = 0; mi < 4; mi++) {
#pragma unroll
        for (int ni = 0; ni < 4; ni++) {
            int row = m0 + wm0 + mi * 16 + g;
            int col = n0 + wn0 + ni * 8 + 2 * tg;
            float b0 = bias[col], b1 = bias[col + 1];
            if (TF32OUT) {
                unsigned* Cu = (unsigned*)Cmat;
                uint2 o0 = {f2tf(acc[mi][ni][0] + b0), f2tf(acc[mi][ni][1] + b1)};
                uint2 o1 = {f2tf(acc[mi][ni][2] + b0), f2tf(acc[mi][ni][3] + b1)};
                *(uint2*)&Cu[(size_t)row * N + col] = o0;
                *(uint2*)&Cu[(size_t)(row + 8) * N + col] = o1;
            } else {
                float* Cf = (float*)Cmat;
                float2 o0 = {acc[mi][ni][0] + b0, acc[mi][ni][1] + b1};
                float2 o1 = {acc[mi][ni][2] + b0, acc[mi][ni][3] + b1};
                *(float2*)&Cf[(size_t)row * N + col] = o0;
                *(float2*)&Cf[(size_t)(row + 8) * N + col] = o1;
            }
        }
    }
}

__global__ __launch_bounds__(256, 2) void gemm_qkv(
    const float* __restrict__ bq, const float* __restrict__ bk,
    const float* __restrict__ bv)
{
    const int z = blockIdx.z;
    const unsigned* A = g_TF + (z == 0 ? X_OFF : S_OFF);
    const unsigned* W = g_TF + W_OFF + (unsigned)z * W_SZ;
    const float* bias = (z == 0) ? bq : (z == 1) ? bk : bv;
    unsigned* out = (z == 0) ? g_Q : (z == 1) ? g_K : g_V;
    gemm_body_cp<true>(A, W, bias, out, C_, C_, blockIdx.x, blockIdx.y);
}

__global__ __launch_bounds__(256, 2) void gemm_out(
    const float* __restrict__ bias, float* __restrict__ Cmat)
{
    gemm_body_cp<false>(g_Y, g_TF + W_OFF + 3u * W_SZ, bias, Cmat,
                        C_, C_, blockIdx.x, blockIdx.y);
}

// ---------------------------------------------------------------------------
// Fused attention, 2 CTAs/SM. Per CTA: 32 q-rows x full 512 k, 64-row chunks.
// smem: Ss[32][516] fp32 | Qs[32][68] | KV[2][64][68]  (109568 B)
// ---------------------------------------------------------------------------
#define SS_PAD 516
#define ATTN_SMEM (32 * SS_PAD * 4 + 32 * 68 * 4 + 2 * 64 * 68 * 4)

__global__ __launch_bounds__(256, 2) void attn_fused(const float* __restrict__ fmap,
                                                     const float* __restrict__ bmap)
{
    extern __shared__ char smraw[];
    float (*Ss)[SS_PAD] = (float (*)[SS_PAD])smraw;
    unsigned (*Ssu)[SS_PAD] = (unsigned (*)[SS_PAD])smraw;
    unsigned (*Qs)[68] = (unsigned (*)[68])(smraw + 32 * SS_PAD * 4);
    unsigned (*KV)[64][68] =
        (unsigned (*)[64][68])(smraw + 32 * SS_PAD * 4 + 32 * 68 * 4);

    const int bh = blockIdx.y, b = bh >> 4, h = bh & 15;
    const int mt = blockIdx.x * 32;
    const unsigned* Qp = g_Q + (size_t)b * T_ * C_ + h * DH_;
    const unsigned* Kp = g_K + (size_t)b * T_ * C_ + h * DH_;
    const unsigned* Vp = g_V + (size_t)b * T_ * C_ + h * DH_;
    const int tid = threadIdx.x, lane = tid & 31, warp = tid >> 5;
    const int g = lane >> 2, tg = lane & 3;

    // prologue: Q tile (32x64) + K chunk 0 (64x64), one cp.async group
#pragma unroll
    for (int it = 0; it < 2; it++) {
        int task = tid + it * 256;
        int row = task >> 4, c4 = (task & 15) << 2;
        CP16(smaddr(&Qs[row][c4]), Qp + (size_t)(mt + row) * C_ + c4);
    }
#pragma unroll
    for (int it = 0; it < 4; it++) {
        int task = tid + it * 256;
        int row = task >> 4, c4 = (task & 15) << 2;
        CP16(smaddr(&KV[0][row][c4]), Kp + (size_t)row * C_ + c4);
    }
    CP_COMMIT();
    CP_WAIT0();
    __syncthreads();

    // ---------------- Phase 1: scores (8 chunks of 64 k) ----------------
    {
        const int wm0 = (warp >> 2) * 16, wn0 = (warp & 3) * 16;
        for (int ci = 0; ci < 8; ci++) {
            const int nt = ci * 64;
            const bool has_next = (ci < 7);
            if (has_next) {
#pragma unroll
                for (int it = 0; it < 4; it++) {
                    int task = tid + it * 256;
                    int row = task >> 4, c4 = (task & 15) << 2;
                    CP16(smaddr(&KV[(ci + 1) & 1][row][c4]),
                         Kp + (size_t)(nt + 64 + row) * C_ + c4);
                }
                CP_COMMIT();
            }

            float acc[2][4] = {};
#pragma unroll
            for (int ks = 0; ks < 8; ks++) {
                const int c = ks * 8;
                unsigned af[4], bf[2][2];
                af[0] = Qs[wm0 + g][c + tg];
                af[1] = Qs[wm0 + g + 8][c + tg];
                af[2] = Qs[wm0 + g][c + tg + 4];
                af[3] = Qs[wm0 + g + 8][c + tg + 4];
#pragma unroll
                for (int ni = 0; ni < 2; ni++) {
                    int n = wn0 + ni * 8 + g;
                    bf[ni][0] = KV[ci & 1][n][c + tg];
                    bf[ni][1] = KV[ci & 1][n][c + tg + 4];
                }
#pragma unroll
                for (int ni = 0; ni < 2; ni++)
                    mma_tf32(acc[ni], af, bf[ni]);
            }

            // epilogue: scale + mask -> Ss
#pragma unroll
            for (int ni = 0; ni < 2; ni++) {
                int kg = nt + wn0 + ni * 8 + 2 * tg;
#pragma unroll
                for (int half = 0; half < 2; half++) {
                    int qlo = wm0 + g + half * 8;
                    int qg = mt + qlo;
                    float v0 = acc[ni][half * 2 + 0] * 0.125f;
                    float v1 = acc[ni][half * 2 + 1] * 0.125f;
                    if (qg < HW_) {
                        if (kg < HW_)
                            v0 *= fmap[((size_t)b * HW_ + qg) * HW_ + kg] *
                                  bmap[((size_t)b * HW_ + kg) * HW_ + qg];
                        if (kg + 1 < HW_)
                            v1 *= fmap[((size_t)b * HW_ + qg) * HW_ + kg + 1] *
                                  bmap[((size_t)b * HW_ + kg + 1) * HW_ + qg];
                    }
                    Ss[qlo][kg] = v0;
                    Ss[qlo][kg + 1] = v1;
                }
            }

            if (has_next) {
                CP_WAIT0();
                __syncthreads();
            }
        }
    }
    __syncthreads();

    // ---------------- Phase 2: softmax (4 rows/warp); async V chunk 0 ----
#pragma unroll
    for (int it = 0; it < 4; it++) {
        int task = tid + it * 256;
        int row = task >> 4, c4 = (task & 15) << 2;
        CP16(smaddr(&KV[0][row][c4]), Vp + (size_t)row * C_ + c4);
    }
    CP_COMMIT();
    {
        int row = warp * 4;
#pragma unroll 1
        for (int r = 0; r < 4; r++, row++) {
            float v[16];
            float m = -1e30f;
#pragma unroll
            for (int j = 0; j < 16; j++) {
                v[j] = Ss[row][lane + 32 * j];
                m = fmaxf(m, v[j]);
            }
#pragma unroll
            for (int o = 16; o > 0; o >>= 1)
                m = fmaxf(m, __shfl_xor_sync(0xffffffffu, m, o));
            float s = 0.f;
#pragma unroll
            for (int j = 0; j < 16; j++) {
                v[j] = __expf(v[j] - m);
                s += v[j];
            }
#pragma unroll
            for (int o = 16; o > 0; o >>= 1)
                s += __shfl_xor_sync(0xffffffffu, s, o);
            float inv = 1.0f / s;
#pragma unroll
            for (int j = 0; j < 16; j++)
                Ssu[row][lane + 32 * j] = f2tf(v[j] * inv);
        }
    }
    CP_WAIT0();
    __syncthreads();

    // ---------------- Phase 3: O = A V (8 chunks of 64 k) ----------------
    {
        const int wm0 = (warp >> 2) * 16, wn0 = (warp & 3) * 16;
        float acc[2][4] = {};
        for (int ci = 0; ci < 8; ci++) {
            const int nt = ci * 64;
            const bool has_next = (ci < 7);
            if (has_next) {
#pragma unroll
                for (int it = 0; it < 4; it++) {
                    int task = tid + it * 256;
                    int row = task >> 4, c4 = (task & 15) << 2;
                    CP16(smaddr(&KV[(ci + 1) & 1][row][c4]),
                         Vp + (size_t)(nt + 64 + row) * C_ + c4);
                }
                CP_COMMIT();
            }
#pragma unroll
            for (int ks = 0; ks < 8; ks++) {
                const int c = ks * 8;
                unsigned af[4], bf[2][2];
                af[0] = Ssu[wm0 + g][nt + c + tg];
                af[1] = Ssu[wm0 + g + 8][nt + c + tg];
                af[2] = Ssu[wm0 + g][nt + c + tg + 4];
                af[3] = Ssu[wm0 + g + 8][nt + c + tg + 4];
#pragma unroll
                for (int ni = 0; ni < 2; ni++) {
                    int n = wn0 + ni * 8 + g;
                    bf[ni][0] = KV[ci & 1][c + tg][n];
                    bf[ni][1] = KV[ci & 1][c + tg + 4][n];
                }
#pragma unroll
                for (int ni = 0; ni < 2; ni++)
                    mma_tf32(acc[ni], af, bf[ni]);
            }
            if (has_next) {
                CP_WAIT0();
                __syncthreads();
            }
        }

#pragma unroll
        for (int ni = 0; ni < 2; ni++) {
            int qg = mt + wm0 + g;
            int d = wn0 + ni * 8 + 2 * tg;
            unsigned* yp = g_Y + (size_t)(b * T_ + qg) * C_ + h * DH_ + d;
            uint2 o0 = {f2tf(acc[ni][0]), f2tf(acc[ni][1])};
            uint2 o1 = {f2tf(acc[ni][2]), f2tf(acc[ni][3])};
            *(uint2*)yp = o0;
            *(uint2*)(yp + (size_t)8 * C_) = o1;
        }
    }
}

// ---------------------------------------------------------------------------
extern "C" void kernel_launch(void* const* d_in, const int* in_sizes, int n_in,
                              void* d_out, int out_size)
{
    const float* x    = (const float*)d_in[0];
    const float* src  = (const float*)d_in[1];
    const float* fmap = (const float*)d_in[2];
    const float* bmap = (const float*)d_in[3];
    const float* Wq   = (const float*)d_in[4];
    const float* bq   = (const float*)d_in[5];
    const float* Wk   = (const float*)d_in[6];
    const float* bk   = (const float*)d_in[7];
    const float* Wv   = (const float*)d_in[8];
    const float* bv   = (const float*)d_in[9];
    const float* Wp   = (const float*)d_in[10];
    const float* bp   = (const float*)d_in[11];
    float* out = (float*)d_out;

    cudaFuncSetAttribute(gemm_qkv, cudaFuncAttributeMaxDynamicSharedMemorySize,
                         GEMM_SMEM);
    cudaFuncSetAttribute(gemm_out, cudaFuncAttributeMaxDynamicSharedMemorySize,
                         GEMM_SMEM);
    cudaFuncSetAttribute(attn_fused, cudaFuncAttributeMaxDynamicSharedMemorySize,
                         ATTN_SMEM);

    prep_tf32<<<12288, 256>>>((const float4*)x, (const float4*)src,
                              (const float4*)Wq, (const float4*)Wk,
                              (const float4*)Wv, (const float4*)Wp);

    const int M = B_ * T_;                  // 4096
    dim3 gQKV(C_ / 128, M / 128, 3);        // 8 x 32 x 3
    gemm_qkv<<<gQKV, 256, GEMM_SMEM>>>(bq, bk, bv);

    dim3 gAttn(T_ / 32, B_ * NH_);          // 16 x 128 = 2048 CTAs
    attn_fused<<<gAttn, 256, ATTN_SMEM>>>(fmap, bmap);

    dim3 gProj(C_ / 128, M / 128);          // 8 x 32
    gemm_out<<<gProj, 256, GEMM_SMEM>>>(bp, out);
}

// round 10
// speedup vs baseline: 3.7887x; 1.4299x over previous
#include <cuda_runtime.h>
#include <cuda_fp16.h>
#include <cstdint>

#define B_  8
#define T_  512
#define C_  1024
#define NH_ 16
#define DH_ 64
#define HW_ 256

// fp16 scratch: [x:4M][src:4M][Wq:1M][Wk:1M][Wv:1M][Wp:1M] halves
#define X_OFF  0u
#define S_OFF  4194304u
#define W_OFF  8388608u
#define W_SZ   1048576u
__device__ __half g_H[12 * 1048576];
__device__ __half g_Q[B_ * T_ * C_];
__device__ __half g_K[B_ * T_ * C_];
__device__ __half g_V[B_ * T_ * C_];
__device__ __half g_Y[B_ * T_ * C_];

__device__ __forceinline__ unsigned packh2(float a, float b) {
    __half2 h = __floats2half2_rn(a, b);   // lo=a, hi=b
    return *(unsigned*)&h;
}

__device__ __forceinline__ void mma_f16(float* c, const unsigned* a, const unsigned* b) {
    asm volatile(
        "mma.sync.aligned.m16n8k16.row.col.f32.f16.f16.f32 "
        "{%0,%1,%2,%3},{%4,%5,%6,%7},{%8,%9},{%0,%1,%2,%3};"
        : "+f"(c[0]), "+f"(c[1]), "+f"(c[2]), "+f"(c[3])
        : "r"(a[0]), "r"(a[1]), "r"(a[2]), "r"(a[3]), "r"(b[0]), "r"(b[1]));
}

__device__ __forceinline__ unsigned smaddr(const void* p) {
    unsigned a;
    asm("{ .reg .u64 t; cvta.to.shared.u64 t, %1; cvt.u32.u64 %0, t; }"
        : "=r"(a) : "l"(p));
    return a;
}
#define CP16(dst, src) \
    asm volatile("cp.async.cg.shared.global [%0], [%1], 16;" :: "r"(dst), "l"(src))
#define CP_COMMIT() asm volatile("cp.async.commit_group;" ::: "memory")
#define CP_WAIT0()  asm volatile("cp.async.wait_group 0;" ::: "memory")

__device__ __forceinline__ void ldmx2t(unsigned& r0, unsigned& r1, unsigned a) {
    asm volatile("ldmatrix.sync.aligned.m8n8.x2.trans.shared.b16 {%0,%1}, [%2];"
                 : "=r"(r0), "=r"(r1) : "r"(a));
}

// ---------------------------------------------------------------------------
// Prep: fp32 -> fp16 once.
// ---------------------------------------------------------------------------
__global__ __launch_bounds__(256) void prep_fp16(
    const float4* __restrict__ x, const float4* __restrict__ src,
    const float4* __restrict__ wq, const float4* __restrict__ wk,
    const float4* __restrict__ wv, const float4* __restrict__ wp)
{
    unsigned i = blockIdx.x * 256 + threadIdx.x;   // float4 index < 3145728
    const float4* s; unsigned off;
    if      (i < 1048576u) { s = x;   off = i; }
    else if (i < 2097152u) { s = src; off = i - 1048576u; }
    else if (i < 2359296u) { s = wq;  off = i - 2097152u; }
    else if (i < 2621440u) { s = wk;  off = i - 2359296u; }
    else if (i < 2883584u) { s = wv;  off = i - 2621440u; }
    else                   { s = wp;  off = i - 2883584u; }
    float4 v = s[off];
    uint2 u = {packh2(v.x, v.y), packh2(v.z, v.w)};
    ((uint2*)g_H)[i] = u;
}

// ---------------------------------------------------------------------------
// fp16 GEMM: C[m,n] = sum_k A[m,k]*W[n,k] + bias[n].
// 128x128x32 tiles, cp.async double buffer.
// smem halves: As[2][128][40] | Bs[2][128][40]  (40960 B); row = 20 words.
// ---------------------------------------------------------------------------
#define GEMM_SMEM 40960

template <bool H16OUT>
__device__ __forceinline__ void gemm_body_h(
    const __half* __restrict__ A, const __half* __restrict__ W,
    const float* __restrict__ bias, void* __restrict__ Cmat,
    int N, int K, int bx, int by)
{
    extern __shared__ unsigned smw[];
    unsigned* Aw = smw;                 // 2 bufs x 2560 words
    unsigned* Bw = smw + 5120;
    const unsigned smb = smaddr(smw);

    const int tid = threadIdx.x, lane = tid & 31, warp = tid >> 5;
    const int wm0 = (warp >> 2) * 64, wn0 = (warp & 3) * 32;
    const int g = lane >> 2, tg = lane & 3;
    const int m0 = by * 128, n0 = bx * 128;
    const int lrow = tid >> 1, lch = tid & 1;     // staging: 2 chunks each of A,B

    float acc[4][4][4] = {};

    auto fill = [&](int buf, int kt) {
#pragma unroll
        for (int cc = 0; cc < 2; cc++) {
            int ch = lch + cc * 2;
            unsigned d = smb + (unsigned)buf * 10240u + (unsigned)(lrow * 80 + ch * 16);
            CP16(d, A + (size_t)(m0 + lrow) * K + kt * 32 + ch * 8);
            CP16(d + 20480u, W + (size_t)(n0 + lrow) * K + kt * 32 + ch * 8);
        }
    };

    fill(0, 0);
    CP_COMMIT();
    CP_WAIT0();
    __syncthreads();

    int cur = 0;
    const int NT = K / 32;
    for (int kt = 0; kt < NT; kt++) {
        const bool has_next = (kt + 1 < NT);
        if (has_next) { fill(cur ^ 1, kt + 1); CP_COMMIT(); }
        const unsigned* Ac = Aw + cur * 2560;
        const unsigned* Bc = Bw + cur * 2560;
#pragma unroll
        for (int ks = 0; ks < 2; ks++) {
            const int c = ks * 8;
            unsigned af[4][4], bf[4][2];
#pragma unroll
            for (int mi = 0; mi < 4; mi++) {
                int r = wm0 + mi * 16;
                af[mi][0] = Ac[(r + g) * 20 + c + tg];
                af[mi][1] = Ac[(r + g + 8) * 20 + c + tg];
                af[mi][2] = Ac[(r + g) * 20 + c + tg + 4];
                af[mi][3] = Ac[(r + g + 8) * 20 + c + tg + 4];
            }
#pragma unroll
            for (int ni = 0; ni < 4; ni++) {
                int n = wn0 + ni * 8 + g;
                bf[ni][0] = Bc[n * 20 + c + tg];
                bf[ni][1] = Bc[n * 20 + c + tg + 4];
            }
#pragma unroll
            for (int mi = 0; mi < 4; mi++)
#pragma unroll
                for (int ni = 0; ni < 4; ni++)
                    mma_f16(acc[mi][ni], af[mi], bf[ni]);
        }
        if (has_next) {
            CP_WAIT0();
            __syncthreads();
        }
        cur ^= 1;
    }

#pragma unroll
    for (int mi = 0; mi < 4; mi++) {
#pragma unroll
        for (int ni = 0; ni < 4; ni++) {
            int row = m0 + wm0 + mi * 16 + g;
            int col = n0 + wn0 + ni * 8 + 2 * tg;
            float b0 = bias[col], b1 = bias[col + 1];
            if (H16OUT) {
                unsigned* Cu = (unsigned*)Cmat;
                Cu[((size_t)row * N + col) >> 1] =
                    packh2(acc[mi][ni][0] + b0, acc[mi][ni][1] + b1);
                Cu[((size_t)(row + 8) * N + col) >> 1] =
                    packh2(acc[mi][ni][2] + b0, acc[mi][ni][3] + b1);
            } else {
                float* Cf = (float*)Cmat;
                float2 o0 = {acc[mi][ni][0] + b0, acc[mi][ni][1] + b1};
                float2 o1 = {acc[mi][ni][2] + b0, acc[mi][ni][3] + b1};
                *(float2*)&Cf[(size_t)row * N + col] = o0;
                *(float2*)&Cf[(size_t)(row + 8) * N + col] = o1;
            }
        }
    }
}

__global__ __launch_bounds__(256, 2) void gemm_qkv(
    const float* __restrict__ bq, const float* __restrict__ bk,
    const float* __restrict__ bv)
{
    const int z = blockIdx.z;
    const __half* A = g_H + (z == 0 ? X_OFF : S_OFF);
    const __half* W = g_H + W_OFF + (unsigned)z * W_SZ;
    const float* bias = (z == 0) ? bq : (z == 1) ? bk : bv;
    __half* out = (z == 0) ? g_Q : (z == 1) ? g_K : g_V;
    gemm_body_h<true>(A, W, bias, out, C_, C_, blockIdx.x, blockIdx.y);
}

__global__ __launch_bounds__(256, 2) void gemm_out(
    const float* __restrict__ bias, float* __restrict__ Cmat)
{
    gemm_body_h<false>(g_Y, g_H + W_OFF + 3u * W_SZ, bias, Cmat,
                       C_, C_, blockIdx.x, blockIdx.y);
}

// ---------------------------------------------------------------------------
// Fused attention fp16. Per CTA: 32 q-rows x full 512 k, 64-token chunks.
// smem: Ss[32][516] f32 (66048) | Qs[32][72] h (4608) | KV[2][64][72] h (18432)
// ---------------------------------------------------------------------------
#define SS_PAD 516
#define ATTN_SMEM (32 * SS_PAD * 4 + 32 * 72 * 2 + 2 * 64 * 72 * 2)

__global__ __launch_bounds__(256, 2) void attn_fused(const float* __restrict__ fmap,
                                                     const float* __restrict__ bmap)
{
    extern __shared__ char smraw[];
    float (*Ss)[SS_PAD] = (float (*)[SS_PAD])smraw;
    char* qbase = smraw + 32 * SS_PAD * 4;
    char* kvbase = qbase + 32 * 72 * 2;
    const unsigned* Qw = (const unsigned*)qbase;      // row stride 36 words
    const unsigned* KVw = (const unsigned*)kvbase;    // buf 2304 w, row 36 w
    const unsigned qsm = smaddr(qbase);
    const unsigned kvsm = smaddr(kvbase);

    const int bh = blockIdx.y, b = bh >> 4, h = bh & 15;
    const int mt = blockIdx.x * 32;
    const __half* Qp = g_Q + (size_t)b * T_ * C_ + h * DH_;
    const __half* Kp = g_K + (size_t)b * T_ * C_ + h * DH_;
    const __half* Vp = g_V + (size_t)b * T_ * C_ + h * DH_;
    const int tid = threadIdx.x, lane = tid & 31, warp = tid >> 5;
    const int g = lane >> 2, tg = lane & 3;

    auto fill_kv = [&](int buf, const __half* src, int tok0) {
        int row = tid >> 2;
#pragma unroll
        for (int cc = 0; cc < 2; cc++) {
            int ch = (tid & 3) + cc * 4;
            CP16(kvsm + (unsigned)(buf * 9216 + row * 144 + ch * 16),
                 src + (size_t)(tok0 + row) * C_ + ch * 8);
        }
    };

    // prologue: Q tile (32x64h) + K chunk 0
    {
        int row = tid >> 3, ch = tid & 7;
        CP16(qsm + (unsigned)(row * 144 + ch * 16),
             Qp + (size_t)(mt + row) * C_ + ch * 8);
    }
    fill_kv(0, Kp, 0);
    CP_COMMIT();
    CP_WAIT0();
    __syncthreads();

    // ---------------- Phase 1: scores (8 chunks of 64 tokens) -------------
    {
        const int wm0 = (warp >> 2) * 16, wn0 = (warp & 3) * 16;
        for (int ci = 0; ci < 8; ci++) {
            const int nt = ci * 64;
            const bool has_next = (ci < 7);
            if (has_next) { fill_kv((ci + 1) & 1, Kp, nt + 64); CP_COMMIT(); }

            float acc[2][4] = {};
            const unsigned* Kc = KVw + (ci & 1) * 2304;
#pragma unroll
            for (int ks = 0; ks < 4; ks++) {
                const int c = ks * 8;
                unsigned af[4], bf[2][2];
                af[0] = Qw[(wm0 + g) * 36 + c + tg];
                af[1] = Qw[(wm0 + g + 8) * 36 + c + tg];
                af[2] = Qw[(wm0 + g) * 36 + c + tg + 4];
                af[3] = Qw[(wm0 + g + 8) * 36 + c + tg + 4];
#pragma unroll
                for (int ni = 0; ni < 2; ni++) {
                    int n = wn0 + ni * 8 + g;
                    bf[ni][0] = Kc[n * 36 + c + tg];
                    bf[ni][1] = Kc[n * 36 + c + tg + 4];
                }
#pragma unroll
                for (int ni = 0; ni < 2; ni++)
                    mma_f16(acc[ni], af, bf[ni]);
            }

            // epilogue: scale + mask -> Ss (fp32)
#pragma unroll
            for (int ni = 0; ni < 2; ni++) {
                int kg = nt + wn0 + ni * 8 + 2 * tg;
#pragma unroll
                for (int half = 0; half < 2; half++) {
                    int qlo = wm0 + g + half * 8;
                    int qg = mt + qlo;
                    float v0 = acc[ni][half * 2 + 0] * 0.125f;
                    float v1 = acc[ni][half * 2 + 1] * 0.125f;
                    if (qg < HW_) {
                        if (kg < HW_)
                            v0 *= fmap[((size_t)b * HW_ + qg) * HW_ + kg] *
                                  bmap[((size_t)b * HW_ + kg) * HW_ + qg];
                        if (kg + 1 < HW_)
                            v1 *= fmap[((size_t)b * HW_ + qg) * HW_ + kg + 1] *
                                  bmap[((size_t)b * HW_ + kg + 1) * HW_ + qg];
                    }
                    Ss[qlo][kg] = v0;
                    Ss[qlo][kg + 1] = v1;
                }
            }

            if (has_next) {
                CP_WAIT0();
                __syncthreads();
            }
        }
    }
    __syncthreads();

    // ---------------- Phase 2: softmax -> fp16 pairs overlaid on Ss -------
    fill_kv(0, Vp, 0);     // async V chunk 0 during softmax
    CP_COMMIT();
    {
        int row = warp * 4;
#pragma unroll 1
        for (int r = 0; r < 4; r++, row++) {
            float v[16];
            float m = -1e30f;
#pragma unroll
            for (int j = 0; j < 8; j++) {
                float2 p = *(float2*)&Ss[row][2 * lane + 64 * j];
                v[2 * j] = p.x; v[2 * j + 1] = p.y;
                m = fmaxf(m, fmaxf(p.x, p.y));
            }
#pragma unroll
            for (int o = 16; o > 0; o >>= 1)
                m = fmaxf(m, __shfl_xor_sync(0xffffffffu, m, o));
            float s = 0.f;
#pragma unroll
            for (int j = 0; j < 16; j++) {
                v[j] = __expf(v[j] - m);
                s += v[j];
            }
#pragma unroll
            for (int o = 16; o > 0; o >>= 1)
                s += __shfl_xor_sync(0xffffffffu, s, o);
            float inv = 1.0f / s;
            __syncwarp();   // all reads of this row done before overlay writes
#pragma unroll
            for (int j = 0; j < 8; j++)
                ((unsigned*)&Ss[row][0])[lane + 32 * j] =
                    packh2(v[2 * j] * inv, v[2 * j + 1] * inv);
        }
    }
    CP_WAIT0();
    __syncthreads();

    // ---------------- Phase 3: O = P V (8 chunks of 64 tokens) ------------
    {
        const int wm0 = (warp >> 2) * 16, wn0 = (warp & 3) * 16;
        float acc[2][4] = {};
        for (int ci = 0; ci < 8; ci++) {
            const int nt = ci * 64;
            const bool has_next = (ci < 7);
            if (has_next) { fill_kv((ci + 1) & 1, Vp, nt + 64); CP_COMMIT(); }

            const unsigned vb = kvsm + (unsigned)((ci & 1) * 9216);
#pragma unroll
            for (int ks = 0; ks < 4; ks++) {
                const int c = 16 * ks;
                unsigned af[4];
                const unsigned* P0 = (const unsigned*)&Ss[wm0 + g][0];
                const unsigned* P1 = (const unsigned*)&Ss[wm0 + g + 8][0];
                af[0] = P0[nt / 2 + 8 * ks + tg];
                af[1] = P1[nt / 2 + 8 * ks + tg];
                af[2] = P0[nt / 2 + 8 * ks + tg + 4];
                af[3] = P1[nt / 2 + 8 * ks + tg + 4];
#pragma unroll
                for (int ni = 0; ni < 2; ni++) {
                    int dbase = wn0 + ni * 8;
                    unsigned addr = vb + (unsigned)((c + (lane & 15)) * 144 + dbase * 2);
                    unsigned bf[2];
                    ldmx2t(bf[0], bf[1], addr);
                    mma_f16(acc[ni], af, bf);
                }
            }
            if (has_next) {
                CP_WAIT0();
                __syncthreads();
            }
        }

#pragma unroll
        for (int ni = 0; ni < 2; ni++) {
            int qg = mt + wm0 + g;
            int d = wn0 + ni * 8 + 2 * tg;
            unsigned* yp = (unsigned*)g_Y;
            yp[((size_t)(b * T_ + qg) * C_ + h * DH_ + d) >> 1] =
                packh2(acc[ni][0], acc[ni][1]);
            yp[((size_t)(b * T_ + qg + 8) * C_ + h * DH_ + d) >> 1] =
                packh2(acc[ni][2], acc[ni][3]);
        }
    }
}

// ---------------------------------------------------------------------------
extern "C" void kernel_launch(void* const* d_in, const int* in_sizes, int n_in,
                              void* d_out, int out_size)
{
    const float* x    = (const float*)d_in[0];
    const float* src  = (const float*)d_in[1];
    const float* fmap = (const float*)d_in[2];
    const float* bmap = (const float*)d_in[3];
    const float* Wq   = (const float*)d_in[4];
    const float* bq   = (const float*)d_in[5];
    const float* Wk   = (const float*)d_in[6];
    const float* bk   = (const float*)d_in[7];
    const float* Wv   = (const float*)d_in[8];
    const float* bv   = (const float*)d_in[9];
    const float* Wp   = (const float*)d_in[10];
    const float* bp   = (const float*)d_in[11];
    float* out = (float*)d_out;

    cudaFuncSetAttribute(gemm_qkv, cudaFuncAttributeMaxDynamicSharedMemorySize,
                         GEMM_SMEM);
    cudaFuncSetAttribute(gemm_out, cudaFuncAttributeMaxDynamicSharedMemorySize,
                         GEMM_SMEM);
    cudaFuncSetAttribute(attn_fused, cudaFuncAttributeMaxDynamicSharedMemorySize,
                         ATTN_SMEM);

    prep_fp16<<<12288, 256>>>((const float4*)x, (const float4*)src,
                              (const float4*)Wq, (const float4*)Wk,
                              (const float4*)Wv, (const float4*)Wp);

    const int M = B_ * T_;                  // 4096
    dim3 gQKV(C_ / 128, M / 128, 3);        // 8 x 32 x 3
    gemm_qkv<<<gQKV, 256, GEMM_SMEM>>>(bq, bk, bv);

    dim3 gAttn(T_ / 32, B_ * NH_);          // 16 x 128 = 2048 CTAs
    attn_fused<<<gAttn, 256, ATTN_SMEM>>>(fmap, bmap);

    dim3 gProj(C_ / 128, M / 128);          // 8 x 32
    gemm_out<<<gProj, 256, GEMM_SMEM>>>(bp, out);
}

// round 11
// speedup vs baseline: 3.9958x; 1.0547x over previous
#include <cuda_runtime.h>
#include <cuda_fp16.h>
#include <cstdint>

#define B_  8
#define T_  512
#define C_  1024
#define NH_ 16
#define DH_ 64
#define HW_ 256

// fp16 scratch: [x:4M][src:4M][Wq:1M][Wk:1M][Wv:1M][Wp:1M] halves
#define X_OFF  0u
#define S_OFF  4194304u
#define W_OFF  8388608u
#define W_SZ   1048576u
__device__ __half g_H[12 * 1048576];
__device__ __half g_Q[B_ * T_ * C_];
__device__ __half g_K[B_ * T_ * C_];
__device__ __half g_V[B_ * T_ * C_];
__device__ __half g_Y[B_ * T_ * C_];

__device__ __forceinline__ unsigned packh2(float a, float b) {
    __half2 h = __floats2half2_rn(a, b);
    return *(unsigned*)&h;
}

__device__ __forceinline__ void mma_f16(float* c, const unsigned* a, const unsigned* b) {
    asm volatile(
        "mma.sync.aligned.m16n8k16.row.col.f32.f16.f16.f32 "
        "{%0,%1,%2,%3},{%4,%5,%6,%7},{%8,%9},{%0,%1,%2,%3};"
        : "+f"(c[0]), "+f"(c[1]), "+f"(c[2]), "+f"(c[3])
        : "r"(a[0]), "r"(a[1]), "r"(a[2]), "r"(a[3]), "r"(b[0]), "r"(b[1]));
}

__device__ __forceinline__ unsigned smaddr(const void* p) {
    unsigned a;
    asm("{ .reg .u64 t; cvta.to.shared.u64 t, %1; cvt.u32.u64 %0, t; }"
        : "=r"(a) : "l"(p));
    return a;
}
#define CP16(dst, src) \
    asm volatile("cp.async.cg.shared.global [%0], [%1], 16;" :: "r"(dst), "l"(src))
#define CP_COMMIT() asm volatile("cp.async.commit_group;" ::: "memory")
#define CP_WAIT0()  asm volatile("cp.async.wait_group 0;" ::: "memory")

__device__ __forceinline__ void ldmx4(unsigned& r0, unsigned& r1, unsigned& r2,
                                      unsigned& r3, unsigned a) {
    asm volatile("ldmatrix.sync.aligned.m8n8.x4.shared.b16 {%0,%1,%2,%3}, [%4];"
                 : "=r"(r0), "=r"(r1), "=r"(r2), "=r"(r3) : "r"(a));
}
__device__ __forceinline__ void ldmx2t(unsigned& r0, unsigned& r1, unsigned a) {
    asm volatile("ldmatrix.sync.aligned.m8n8.x2.trans.shared.b16 {%0,%1}, [%2];"
                 : "=r"(r0), "=r"(r1) : "r"(a));
}

// ---------------------------------------------------------------------------
// Prep: fp32 -> fp16 once.
// ---------------------------------------------------------------------------
__global__ __launch_bounds__(256) void prep_fp16(
    const float4* __restrict__ x, const float4* __restrict__ src,
    const float4* __restrict__ wq, const float4* __restrict__ wk,
    const float4* __restrict__ wv, const float4* __restrict__ wp)
{
    unsigned i = blockIdx.x * 256 + threadIdx.x;
    const float4* s; unsigned off;
    if      (i < 1048576u) { s = x;   off = i; }
    else if (i < 2097152u) { s = src; off = i - 1048576u; }
    else if (i < 2359296u) { s = wq;  off = i - 2097152u; }
    else if (i < 2621440u) { s = wk;  off = i - 2359296u; }
    else if (i < 2883584u) { s = wv;  off = i - 2621440u; }
    else                   { s = wp;  off = i - 2883584u; }
    float4 v = s[off];
    uint2 u = {packh2(v.x, v.y), packh2(v.z, v.w)};
    ((uint2*)g_H)[i] = u;
}

// ---------------------------------------------------------------------------
// fp16 GEMM: C[m,n] = sum_k A[m,k]*W[n,k] + bias[n].
// 128x128 tile, BK=64, double buffer, ldmatrix fragments.
// smem: A[2][128][72]h | B[2][128][72]h = 73728 B. Row stride 144 B.
// ---------------------------------------------------------------------------
#define GEMM_SMEM 73728
#define ABUF 18432u

template <bool H16OUT>
__device__ __forceinline__ void gemm_body_h(
    const __half* __restrict__ A, const __half* __restrict__ W,
    const float* __restrict__ bias, void* __restrict__ Cmat,
    int N, int K, int bx, int by)
{
    extern __shared__ char smc[];
    const unsigned smA = smaddr(smc);
    const unsigned smB = smA + 2 * ABUF;

    const int tid = threadIdx.x, lane = tid & 31, warp = tid >> 5;
    const int wm0 = (warp >> 2) * 64, wn0 = (warp & 3) * 32;
    const int g = lane >> 2, tg = lane & 3;
    const int m0 = by * 128, n0 = bx * 128;
    const int lrow = tid >> 1, lch4 = (tid & 1) * 4;

    float acc[4][4][4] = {};

    auto fill = [&](int buf, int kt) {
#pragma unroll
        for (int cc = 0; cc < 4; cc++) {
            int ch = lch4 + cc;
            unsigned d = (unsigned)(buf * ABUF + lrow * 144 + ch * 16);
            CP16(smA + d, A + (size_t)(m0 + lrow) * K + kt * 64 + ch * 8);
            CP16(smB + d, W + (size_t)(n0 + lrow) * K + kt * 64 + ch * 8);
        }
    };

    fill(0, 0);
    CP_COMMIT();
    CP_WAIT0();
    __syncthreads();

    // fragment ldmatrix addressing
    const int arow = lane & 15, ak = (lane >> 4) * 8;       // A: x4
    const int brow = (lane & 7) + (lane >> 4) * 8;          // B: x4 (2 ni per)
    const int bk = ((lane >> 3) & 1) * 8;

    int cur = 0;
    const int NT = K / 64;
    for (int kt = 0; kt < NT; kt++) {
        const bool has_next = (kt + 1 < NT);
        if (has_next) { fill(cur ^ 1, kt + 1); CP_COMMIT(); }
        const unsigned ab = smA + (unsigned)(cur * ABUF);
        const unsigned bb = smB + (unsigned)(cur * ABUF);
#pragma unroll
        for (int ks = 0; ks < 4; ks++) {
            const int c = ks * 16;   // halves
            unsigned af[4][4], bf[4][2];
#pragma unroll
            for (int mi = 0; mi < 4; mi++)
                ldmx4(af[mi][0], af[mi][1], af[mi][2], af[mi][3],
                      ab + (unsigned)((wm0 + mi * 16 + arow) * 144 + (c + ak) * 2));
#pragma unroll
            for (int np = 0; np < 2; np++)
                ldmx4(bf[2 * np][0], bf[2 * np][1], bf[2 * np + 1][0], bf[2 * np + 1][1],
                      bb + (unsigned)((wn0 + np * 16 + brow) * 144 + (c + bk) * 2));
#pragma unroll
            for (int mi = 0; mi < 4; mi++)
#pragma unroll
                for (int ni = 0; ni < 4; ni++)
                    mma_f16(acc[mi][ni], af[mi], bf[ni]);
        }
        if (has_next) {
            CP_WAIT0();
            __syncthreads();
        }
        cur ^= 1;
    }

#pragma unroll
    for (int mi = 0; mi < 4; mi++) {
#pragma unroll
        for (int ni = 0; ni < 4; ni++) {
            int row = m0 + wm0 + mi * 16 + g;
            int col = n0 + wn0 + ni * 8 + 2 * tg;
            float b0 = bias[col], b1 = bias[col + 1];
            if (H16OUT) {
                unsigned* Cu = (unsigned*)Cmat;
                Cu[((size_t)row * N + col) >> 1] =
                    packh2(acc[mi][ni][0] + b0, acc[mi][ni][1] + b1);
                Cu[((size_t)(row + 8) * N + col) >> 1] =
                    packh2(acc[mi][ni][2] + b0, acc[mi][ni][3] + b1);
            } else {
                float* Cf = (float*)Cmat;
                float2 o0 = {acc[mi][ni][0] + b0, acc[mi][ni][1] + b1};
                float2 o1 = {acc[mi][ni][2] + b0, acc[mi][ni][3] + b1};
                *(float2*)&Cf[(size_t)row * N + col] = o0;
                *(float2*)&Cf[(size_t)(row + 8) * N + col] = o1;
            }
        }
    }
}

__global__ __launch_bounds__(256, 2) void gemm_qkv(
    const float* __restrict__ bq, const float* __restrict__ bk,
    const float* __restrict__ bv)
{
    const int z = blockIdx.z;
    const __half* A = g_H + (z == 0 ? X_OFF : S_OFF);
    const __half* W = g_H + W_OFF + (unsigned)z * W_SZ;
    const float* bias = (z == 0) ? bq : (z == 1) ? bk : bv;
    __half* out = (z == 0) ? g_Q : (z == 1) ? g_K : g_V;
    gemm_body_h<true>(A, W, bias, out, C_, C_, blockIdx.x, blockIdx.y);
}

__global__ __launch_bounds__(256, 2) void gemm_out(
    const float* __restrict__ bias, float* __restrict__ Cmat)
{
    gemm_body_h<false>(g_Y, g_H + W_OFF + 3u * W_SZ, bias, Cmat,
                       C_, C_, blockIdx.x, blockIdx.y);
}

// ---------------------------------------------------------------------------
// Fused attention fp16 (unchanged from R10). Per CTA: 32 q x 512 k.
// smem: Ss[32][516] f32 | Qs[32][72] h | KV[2][64][72] h
// ---------------------------------------------------------------------------
#define SS_PAD 516
#define ATTN_SMEM (32 * SS_PAD * 4 + 32 * 72 * 2 + 2 * 64 * 72 * 2)

__global__ __launch_bounds__(256, 2) void attn_fused(const float* __restrict__ fmap,
                                                     const float* __restrict__ bmap)
{
    extern __shared__ char smraw[];
    float (*Ss)[SS_PAD] = (float (*)[SS_PAD])smraw;
    char* qbase = smraw + 32 * SS_PAD * 4;
    char* kvbase = qbase + 32 * 72 * 2;
    const unsigned* Qw = (const unsigned*)qbase;
    const unsigned* KVw = (const unsigned*)kvbase;
    const unsigned qsm = smaddr(qbase);
    const unsigned kvsm = smaddr(kvbase);

    const int bh = blockIdx.y, b = bh >> 4, h = bh & 15;
    const int mt = blockIdx.x * 32;
    const __half* Qp = g_Q + (size_t)b * T_ * C_ + h * DH_;
    const __half* Kp = g_K + (size_t)b * T_ * C_ + h * DH_;
    const __half* Vp = g_V + (size_t)b * T_ * C_ + h * DH_;
    const int tid = threadIdx.x, lane = tid & 31, warp = tid >> 5;
    const int g = lane >> 2, tg = lane & 3;

    auto fill_kv = [&](int buf, const __half* src, int tok0) {
        int row = tid >> 2;
#pragma unroll
        for (int cc = 0; cc < 2; cc++) {
            int ch = (tid & 3) + cc * 4;
            CP16(kvsm + (unsigned)(buf * 9216 + row * 144 + ch * 16),
                 src + (size_t)(tok0 + row) * C_ + ch * 8);
        }
    };

    {
        int row = tid >> 3, ch = tid & 7;
        CP16(qsm + (unsigned)(row * 144 + ch * 16),
             Qp + (size_t)(mt + row) * C_ + ch * 8);
    }
    fill_kv(0, Kp, 0);
    CP_COMMIT();
    CP_WAIT0();
    __syncthreads();

    // Phase 1: scores
    {
        const int wm0 = (warp >> 2) * 16, wn0 = (warp & 3) * 16;
        for (int ci = 0; ci < 8; ci++) {
            const int nt = ci * 64;
            const bool has_next = (ci < 7);
            if (has_next) { fill_kv((ci + 1) & 1, Kp, nt + 64); CP_COMMIT(); }

            float acc[2][4] = {};
            const unsigned* Kc = KVw + (ci & 1) * 2304;
#pragma unroll
            for (int ks = 0; ks < 4; ks++) {
                const int c = ks * 8;
                unsigned af[4], bf[2][2];
                af[0] = Qw[(wm0 + g) * 36 + c + tg];
                af[1] = Qw[(wm0 + g + 8) * 36 + c + tg];
                af[2] = Qw[(wm0 + g) * 36 + c + tg + 4];
                af[3] = Qw[(wm0 + g + 8) * 36 + c + tg + 4];
#pragma unroll
                for (int ni = 0; ni < 2; ni++) {
                    int n = wn0 + ni * 8 + g;
                    bf[ni][0] = Kc[n * 36 + c + tg];
                    bf[ni][1] = Kc[n * 36 + c + tg + 4];
                }
#pragma unroll
                for (int ni = 0; ni < 2; ni++)
                    mma_f16(acc[ni], af, bf[ni]);
            }

#pragma unroll
            for (int ni = 0; ni < 2; ni++) {
                int kg = nt + wn0 + ni * 8 + 2 * tg;
#pragma unroll
                for (int half = 0; half < 2; half++) {
                    int qlo = wm0 + g + half * 8;
                    int qg = mt + qlo;
                    float v0 = acc[ni][half * 2 + 0] * 0.125f;
                    float v1 = acc[ni][half * 2 + 1] * 0.125f;
                    if (qg < HW_) {
                        if (kg < HW_)
                            v0 *= fmap[((size_t)b * HW_ + qg) * HW_ + kg] *
                                  bmap[((size_t)b * HW_ + kg) * HW_ + qg];
                        if (kg + 1 < HW_)
                            v1 *= fmap[((size_t)b * HW_ + qg) * HW_ + kg + 1] *
                                  bmap[((size_t)b * HW_ + kg + 1) * HW_ + qg];
                    }
                    Ss[qlo][kg] = v0;
                    Ss[qlo][kg + 1] = v1;
                }
            }

            if (has_next) {
                CP_WAIT0();
                __syncthreads();
            }
        }
    }
    __syncthreads();

    // Phase 2: softmax -> fp16 pairs overlaid on Ss
    fill_kv(0, Vp, 0);
    CP_COMMIT();
    {
        int row = warp * 4;
#pragma unroll 1
        for (int r = 0; r < 4; r++, row++) {
            float v[16];
            float m = -1e30f;
#pragma unroll
            for (int j = 0; j < 8; j++) {
                float2 p = *(float2*)&Ss[row][2 * lane + 64 * j];
                v[2 * j] = p.x; v[2 * j + 1] = p.y;
                m = fmaxf(m, fmaxf(p.x, p.y));
            }
#pragma unroll
            for (int o = 16; o > 0; o >>= 1)
                m = fmaxf(m, __shfl_xor_sync(0xffffffffu, m, o));
            float s = 0.f;
#pragma unroll
            for (int j = 0; j < 16; j++) {
                v[j] = __expf(v[j] - m);
                s += v[j];
            }
#pragma unroll
            for (int o = 16; o > 0; o >>= 1)
                s += __shfl_xor_sync(0xffffffffu, s, o);
            float inv = 1.0f / s;
            __syncwarp();
#pragma unroll
            for (int j = 0; j < 8; j++)
                ((unsigned*)&Ss[row][0])[lane + 32 * j] =
                    packh2(v[2 * j] * inv, v[2 * j + 1] * inv);
        }
    }
    CP_WAIT0();
    __syncthreads();

    // Phase 3: O = P V
    {
        const int wm0 = (warp >> 2) * 16, wn0 = (warp & 3) * 16;
        float acc[2][4] = {};
        for (int ci = 0; ci < 8; ci++) {
            const int nt = ci * 64;
            const bool has_next = (ci < 7);
            if (has_next) { fill_kv((ci + 1) & 1, Vp, nt + 64); CP_COMMIT(); }

            const unsigned vb = kvsm + (unsigned)((ci & 1) * 9216);
#pragma unroll
            for (int ks = 0; ks < 4; ks++) {
                const int c = 16 * ks;
                unsigned af[4];
                const unsigned* P0 = (const unsigned*)&Ss[wm0 + g][0];
                const unsigned* P1 = (const unsigned*)&Ss[wm0 + g + 8][0];
                af[0] = P0[nt / 2 + 8 * ks + tg];
                af[1] = P1[nt / 2 + 8 * ks + tg];
                af[2] = P0[nt / 2 + 8 * ks + tg + 4];
                af[3] = P1[nt / 2 + 8 * ks + tg + 4];
#pragma unroll
                for (int ni = 0; ni < 2; ni++) {
                    int dbase = wn0 + ni * 8;
                    unsigned addr = vb + (unsigned)((c + (lane & 15)) * 144 + dbase * 2);
                    unsigned bf[2];
                    ldmx2t(bf[0], bf[1], addr);
                    mma_f16(acc[ni], af, bf);
                }
            }
            if (has_next) {
                CP_WAIT0();
                __syncthreads();
            }
        }

#pragma unroll
        for (int ni = 0; ni < 2; ni++) {
            int qg = mt + wm0 + g;
            int d = wn0 + ni * 8 + 2 * tg;
            unsigned* yp = (unsigned*)g_Y;
            yp[((size_t)(b * T_ + qg) * C_ + h * DH_ + d) >> 1] =
                packh2(acc[ni][0], acc[ni][1]);
            yp[((size_t)(b * T_ + qg + 8) * C_ + h * DH_ + d) >> 1] =
                packh2(acc[ni][2], acc[ni][3]);
        }
    }
}

// ---------------------------------------------------------------------------
extern "C" void kernel_launch(void* const* d_in, const int* in_sizes, int n_in,
                              void* d_out, int out_size)
{
    const float* x    = (const float*)d_in[0];
    const float* src  = (const float*)d_in[1];
    const float* fmap = (const float*)d_in[2];
    const float* bmap = (const float*)d_in[3];
    const float* Wq   = (const float*)d_in[4];
    const float* bq   = (const float*)d_in[5];
    const float* Wk   = (const float*)d_in[6];
    const float* bk   = (const float*)d_in[7];
    const float* Wv   = (const float*)d_in[8];
    const float* bv   = (const float*)d_in[9];
    const float* Wp   = (const float*)d_in[10];
    const float* bp   = (const float*)d_in[11];
    float* out = (float*)d_out;

    cudaFuncSetAttribute(gemm_qkv, cudaFuncAttributeMaxDynamicSharedMemorySize,
                         GEMM_SMEM);
    cudaFuncSetAttribute(gemm_out, cudaFuncAttributeMaxDynamicSharedMemorySize,
                         GEMM_SMEM);
    cudaFuncSetAttribute(attn_fused, cudaFuncAttributeMaxDynamicSharedMemorySize,
                         ATTN_SMEM);

    prep_fp16<<<12288, 256>>>((const float4*)x, (const float4*)src,
                              (const float4*)Wq, (const float4*)Wk,
                              (const float4*)Wv, (const float4*)Wp);

    const int M = B_ * T_;                  // 4096
    dim3 gQKV(C_ / 128, M / 128, 3);        // 8 x 32 x 3
    gemm_qkv<<<gQKV, 256, GEMM_SMEM>>>(bq, bk, bv);

    dim3 gAttn(T_ / 32, B_ * NH_);          // 16 x 128
    attn_fused<<<gAttn, 256, ATTN_SMEM>>>(fmap, bmap);

    dim3 gProj(C_ / 128, M / 128);          // 8 x 32
    gemm_out<<<gProj, 256, GEMM_SMEM>>>(bp, out);
}